// round 3
// baseline (speedup 1.0000x reference)
#include <cuda_runtime.h>
#include <cuda_fp16.h>

// Problem constants (B=1)
#define N_TOK   4096
#define D_MODEL 768
#define H_HEADS 12
#define HDIM    64
#define QKV_N   2304          // 3*D
#define K3_PROJ 2304          // expanded-K for projections
#define ATT_SCALE 0.125f

// ---------------- scratch (device globals; no runtime allocation) ----------
__device__ float  g_qkv[N_TOK * QKV_N];
__device__ float  g_att[N_TOK * D_MODEL];
__device__ __half g_xe   [N_TOK  * K3_PROJ];
__device__ __half g_wqkve[QKV_N  * K3_PROJ];
__device__ __half g_atte [N_TOK  * K3_PROJ];
__device__ __half g_woute[D_MODEL* K3_PROJ];

// ---------------- helpers ---------------------------------------------------
__device__ __forceinline__ void hsplit(float x, __half& h, __half& l) {
    h = __float2half_rn(x);
    l = __float2half_rn(x - __half2float(h));
}
__device__ __forceinline__ unsigned hpack(__half a, __half b) {
    __half2 h2 = __halves2half2(a, b);
    return *reinterpret_cast<unsigned*>(&h2);
}
__device__ __forceinline__ void mma16816(float c[4], const unsigned a[4], const unsigned b[2]) {
    asm volatile(
        "mma.sync.aligned.m16n8k16.row.col.f32.f16.f16.f32 "
        "{%0,%1,%2,%3}, {%4,%5,%6,%7}, {%8,%9}, {%0,%1,%2,%3};\n"
        : "+f"(c[0]), "+f"(c[1]), "+f"(c[2]), "+f"(c[3])
        : "r"(a[0]), "r"(a[1]), "r"(a[2]), "r"(a[3]), "r"(b[0]), "r"(b[1]));
}
__device__ __forceinline__ void ldsm_x4(unsigned r[4], const __half* p) {
    unsigned addr = (unsigned)__cvta_generic_to_shared(p);
    asm volatile("ldmatrix.sync.aligned.m8n8.x4.shared.b16 {%0,%1,%2,%3}, [%4];"
                 : "=r"(r[0]), "=r"(r[1]), "=r"(r[2]), "=r"(r[3]) : "r"(addr));
}

// ---------------- expansion kernels -----------------------------------------
// A-pattern: X[M][K] fp32 -> Xe[M][3K] fp16, triplet {hi,hi,lo}.
__global__ void expandA_kernel(const float* __restrict__ X, __half* __restrict__ Xe,
                               int M, int K)
{
    const int kq = K >> 2;
    int idx = blockIdx.x * blockDim.x + threadIdx.x;
    if (idx >= M * kq) return;
    int m = idx / kq;
    int k0 = (idx - m * kq) * 4;
    float4 v = *(const float4*)(X + (size_t)m * K + k0);
    __half h0,l0,h1,l1,h2,l2,h3,l3;
    hsplit(v.x,h0,l0); hsplit(v.y,h1,l1); hsplit(v.z,h2,l2); hsplit(v.w,h3,l3);
    unsigned* o = (unsigned*)(Xe + (size_t)m * 3 * K + 3 * k0);
    o[0]=hpack(h0,h0); o[1]=hpack(l0,h1); o[2]=hpack(h1,l1);
    o[3]=hpack(h2,h2); o[4]=hpack(l2,h3); o[5]=hpack(h3,l3);
}
// B-pattern + transpose: W[K][N] fp32 -> We[N][3K] fp16, triplet {hi,lo,hi}.
__global__ void expandBT_kernel(const float* __restrict__ W, __half* __restrict__ We,
                                int K, int N)
{
    int idx = blockIdx.x * blockDim.x + threadIdx.x;
    if (idx >= K * N) return;
    int k = idx / N, n = idx - k * N;
    float x = W[(size_t)k * N + n];
    __half h, l; hsplit(x, h, l);
    __half* o = We + (size_t)n * 3 * K + 3 * k;
    o[0] = h; o[1] = l; o[2] = h;
}

// ---------------- HGEMM: C = Ae[M][K3] @ Be[N][K3]^T (+bias) ----------------
template <bool HAS_BIAS>
__global__ __launch_bounds__(256)
void hgemm_kernel(const __half* __restrict__ A, const __half* __restrict__ Bt,
                  const float* __restrict__ bias, float* __restrict__ C,
                  int M, int N, int K3)
{
    constexpr int LDSH = 72;
    __shared__ __align__(16) __half As[128 * LDSH];
    __shared__ __align__(16) __half Bs[128 * LDSH];

    const int tid = threadIdx.x, wid = tid >> 5, lane = tid & 31;
    const int g = lane >> 2, t = lane & 3;
    const int wm = wid & 3, wn = wid >> 2;
    const int m0 = blockIdx.y * 128, n0 = blockIdx.x * 128;
    const int NT = K3 >> 6;

    const __half* Ab = A  + (size_t)m0 * K3;
    const __half* Bb = Bt + (size_t)n0 * K3;

    const int ld_row = tid >> 3;
    const int ld_c16 = (tid & 7) * 8;

    // ldmatrix source pointers
    const __half* aA = As + (wm * 32 + (lane & 15)) * LDSH + (lane >> 4) * 8;
    const __half* bB = Bs + (wn * 64 + ((lane >> 4) << 3) + (lane & 7)) * LDSH
                          + ((lane >> 3) & 1) * 8;

    uint4 ra[4], rb[4];
    #pragma unroll
    for (int i = 0; i < 4; i++) {
        int row = ld_row + i * 32;
        ra[i] = *(const uint4*)(Ab + (size_t)row * K3 + ld_c16);
        rb[i] = *(const uint4*)(Bb + (size_t)row * K3 + ld_c16);
    }
    #pragma unroll
    for (int i = 0; i < 4; i++) {
        int row = ld_row + i * 32;
        *(uint4*)(As + row * LDSH + ld_c16) = ra[i];
        *(uint4*)(Bs + row * LDSH + ld_c16) = rb[i];
    }
    __syncthreads();

    float cf[2][8][4] = {};

    for (int kt = 0; kt < NT; kt++) {
        if (kt + 1 < NT) {
            #pragma unroll
            for (int i = 0; i < 4; i++) {
                int row = ld_row + i * 32;
                ra[i] = *(const uint4*)(Ab + (size_t)row * K3 + (kt + 1) * 64 + ld_c16);
                rb[i] = *(const uint4*)(Bb + (size_t)row * K3 + (kt + 1) * 64 + ld_c16);
            }
        }
        #pragma unroll
        for (int kk = 0; kk < 4; kk++) {
            unsigned af[2][4], bf[4][4];
            #pragma unroll
            for (int mi = 0; mi < 2; mi++)
                ldsm_x4(af[mi], aA + mi * 16 * LDSH + kk * 16);
            #pragma unroll
            for (int np = 0; np < 4; np++)
                ldsm_x4(bf[np], bB + np * 16 * LDSH + kk * 16);
            #pragma unroll
            for (int mi = 0; mi < 2; mi++)
                #pragma unroll
                for (int ni = 0; ni < 8; ni++)
                    mma16816(cf[mi][ni], af[mi], &bf[ni >> 1][(ni & 1) * 2]);
        }
        __syncthreads();
        if (kt + 1 < NT) {
            #pragma unroll
            for (int i = 0; i < 4; i++) {
                int row = ld_row + i * 32;
                *(uint4*)(As + row * LDSH + ld_c16) = ra[i];
                *(uint4*)(Bs + row * LDSH + ld_c16) = rb[i];
            }
            __syncthreads();
        }
    }

    #pragma unroll
    for (int mi = 0; mi < 2; mi++) {
        const int r0 = m0 + wm * 32 + mi * 16 + g;
        #pragma unroll
        for (int ni = 0; ni < 8; ni++) {
            const int col = n0 + wn * 64 + ni * 8 + 2 * t;
            float bv0 = 0.f, bv1 = 0.f;
            if (HAS_BIAS) { bv0 = bias[col]; bv1 = bias[col + 1]; }
            *(float2*)(C + (size_t)r0 * N + col) =
                make_float2(cf[mi][ni][0] + bv0, cf[mi][ni][1] + bv1);
            *(float2*)(C + (size_t)(r0 + 8) * N + col) =
                make_float2(cf[mi][ni][2] + bv0, cf[mi][ni][3] + bv1);
        }
    }
}

// ---------------- Flash attention, fp16-split mma, Br=64 --------------------
// Block = (64-query tile, head). 8 warps: wr=wid&3 -> q-rows wr*16..;
// wc=wid>>2 -> key half (keys wc*32..+31 for S; d-cols wc*32..+31 for O).
// Cross-warp softmax via SMEM reduction buffers. 2 CTAs/SM (103.4 KB smem).
#define SQ 200

__global__ __launch_bounds__(256, 2)
void attn_kernel()
{
    extern __shared__ __align__(16) __half sm[];
    __half* Qe = sm;                    // [64][SQ] A-pattern, pre-scaled
    __half* Ke = Qe + 64 * SQ;          // [64][SQ] B-pattern (key rows)
    __half* Ve = Ke + 64 * SQ;          // [64][SQ] d-major, B-pattern
    __half* Pe = Ve + 64 * SQ;          // [64][SQ] A-pattern
    float* red_mx = (float*)(Pe + 64 * SQ);  // [2][64]
    float* red_rs = red_mx + 128;            // [2][64]

    const int qb = blockIdx.x, h = blockIdx.y;
    const int tid = threadIdx.x, wid = tid >> 5, lane = tid & 31;
    const int g = lane >> 2, t = lane & 3;
    const int wr = wid & 3, wc = wid >> 2;

    // ---- load + expand Q tile (once) ----
    {
        const int r  = tid >> 2;            // 0..63
        const int d0 = (tid & 3) * 16;
        const float* qrow = g_qkv + (size_t)(qb * 64 + r) * QKV_N + h * HDIM + d0;
        unsigned* dst = (unsigned*)(Qe + r * SQ + 3 * d0);
        #pragma unroll
        for (int i = 0; i < 4; i++) {
            float4 v = *(const float4*)(qrow + i * 4);
            __half h0,l0,h1,l1,h2,l2,h3,l3;
            hsplit(v.x * ATT_SCALE, h0,l0); hsplit(v.y * ATT_SCALE, h1,l1);
            hsplit(v.z * ATT_SCALE, h2,l2); hsplit(v.w * ATT_SCALE, h3,l3);
            dst[i*6+0]=hpack(h0,h0); dst[i*6+1]=hpack(l0,h1); dst[i*6+2]=hpack(h1,l1);
            dst[i*6+3]=hpack(h2,h2); dst[i*6+4]=hpack(l2,h3); dst[i*6+5]=hpack(h3,l3);
        }
    }

    // ldmatrix source pointers
    const __half* aQ = Qe + (wr * 16 + (lane & 15)) * SQ + (lane >> 4) * 8;
    const __half* aP = Pe + (wr * 16 + (lane & 15)) * SQ + (lane >> 4) * 8;
    const __half* bK = Ke + (wc * 32 + ((lane >> 4) << 3) + (lane & 7)) * SQ
                          + ((lane >> 3) & 1) * 8;
    const __half* bV = Ve + (wc * 32 + ((lane >> 4) << 3) + (lane & 7)) * SQ
                          + ((lane >> 3) & 1) * 8;

    float of[4][4] = {};
    float m0 = -1e30f, m1 = -1e30f, l0s = 0.f, l1s = 0.f;
    const int r0 = wr * 16 + g;

    for (int kb = 0; kb < N_TOK / 64; kb++) {
        __syncthreads();   // prior iter's PV reads of Ke/Ve done
        // ---- load + expand K, V (64 keys) ----
        {
            const int r  = tid >> 2;
            const int d0 = (tid & 3) * 16;
            const float* krow = g_qkv + (size_t)(kb * 64 + r) * QKV_N + D_MODEL + h * HDIM + d0;
            const float* vrow = krow + D_MODEL;
            unsigned* kdst = (unsigned*)(Ke + r * SQ + 3 * d0);
            #pragma unroll
            for (int i = 0; i < 4; i++) {
                float4 kv = *(const float4*)(krow + i * 4);
                __half h0,l0,h1,l1,h2,l2,h3,l3;
                hsplit(kv.x,h0,l0); hsplit(kv.y,h1,l1); hsplit(kv.z,h2,l2); hsplit(kv.w,h3,l3);
                kdst[i*6+0]=hpack(h0,l0); kdst[i*6+1]=hpack(h0,h1); kdst[i*6+2]=hpack(l1,h1);
                kdst[i*6+3]=hpack(h2,l2); kdst[i*6+4]=hpack(h2,h3); kdst[i*6+5]=hpack(l3,h3);

                float4 vv = *(const float4*)(vrow + i * 4);
                float va[4] = {vv.x, vv.y, vv.z, vv.w};
                #pragma unroll
                for (int e = 0; e < 4; e++) {
                    __half hh, ll; hsplit(va[e], hh, ll);
                    __half* vp = Ve + (d0 + i * 4 + e) * SQ + 3 * r;
                    vp[0] = hh; vp[1] = ll; vp[2] = hh;
                }
            }
        }
        __syncthreads();

        // ---- S = Q @ K^T (expanded K'=192), warp slice 16 x 32 ----
        float sf[4][4] = {};
        #pragma unroll
        for (int kk = 0; kk < 12; kk++) {
            unsigned a[4];
            ldsm_x4(a, aQ + kk * 16);
            #pragma unroll
            for (int np = 0; np < 2; np++) {
                unsigned b[4];
                ldsm_x4(b, bK + np * 16 * SQ + kk * 16);
                mma16816(sf[np * 2 + 0], a, &b[0]);
                mma16816(sf[np * 2 + 1], a, &b[2]);
            }
        }

        // ---- cross-warp online softmax ----
        float mx0 = -1e30f, mx1 = -1e30f;
        #pragma unroll
        for (int n = 0; n < 4; n++) {
            mx0 = fmaxf(mx0, fmaxf(sf[n][0], sf[n][1]));
            mx1 = fmaxf(mx1, fmaxf(sf[n][2], sf[n][3]));
        }
        mx0 = fmaxf(mx0, __shfl_xor_sync(0xffffffffu, mx0, 1));
        mx0 = fmaxf(mx0, __shfl_xor_sync(0xffffffffu, mx0, 2));
        mx1 = fmaxf(mx1, __shfl_xor_sync(0xffffffffu, mx1, 1));
        mx1 = fmaxf(mx1, __shfl_xor_sync(0xffffffffu, mx1, 2));
        if (t == 0) {
            red_mx[wc * 64 + r0]     = mx0;
            red_mx[wc * 64 + r0 + 8] = mx1;
        }
        __syncthreads();

        const float mj0 = fmaxf(red_mx[r0],     red_mx[64 + r0]);
        const float mj1 = fmaxf(red_mx[r0 + 8], red_mx[64 + r0 + 8]);
        const float mn0 = fmaxf(m0, mj0), mn1 = fmaxf(m1, mj1);
        const float cr0 = __expf(m0 - mn0), cr1 = __expf(m1 - mn1);
        float rs0 = 0.f, rs1 = 0.f;

        __half* prow0 = Pe + (size_t)r0 * SQ;
        __half* prow1 = prow0 + 8 * SQ;
        #pragma unroll
        for (int n = 0; n < 4; n++) {
            float p00 = __expf(sf[n][0] - mn0);
            float p01 = __expf(sf[n][1] - mn0);
            float p10 = __expf(sf[n][2] - mn1);
            float p11 = __expf(sf[n][3] - mn1);
            rs0 += p00 + p01;
            rs1 += p10 + p11;
            const int j0 = wc * 32 + n * 8 + 2 * t;   // even
            __half a0,b0,a1,b1;
            hsplit(p00, a0, b0); hsplit(p01, a1, b1);
            unsigned* w0 = (unsigned*)(prow0 + 3 * j0);
            w0[0] = hpack(a0, a0); w0[1] = hpack(b0, a1); w0[2] = hpack(a1, b1);
            hsplit(p10, a0, b0); hsplit(p11, a1, b1);
            unsigned* w1 = (unsigned*)(prow1 + 3 * j0);
            w1[0] = hpack(a0, a0); w1[1] = hpack(b0, a1); w1[2] = hpack(a1, b1);
        }
        rs0 += __shfl_xor_sync(0xffffffffu, rs0, 1);
        rs0 += __shfl_xor_sync(0xffffffffu, rs0, 2);
        rs1 += __shfl_xor_sync(0xffffffffu, rs1, 1);
        rs1 += __shfl_xor_sync(0xffffffffu, rs1, 2);
        if (t == 0) {
            red_rs[wc * 64 + r0]     = rs0;
            red_rs[wc * 64 + r0 + 8] = rs1;
        }
        __syncthreads();   // also makes Pe visible to both key-half warps

        const float rt0 = red_rs[r0] + red_rs[64 + r0];
        const float rt1 = red_rs[r0 + 8] + red_rs[64 + r0 + 8];
        l0s = l0s * cr0 + rt0;  m0 = mn0;
        l1s = l1s * cr1 + rt1;  m1 = mn1;
        #pragma unroll
        for (int n = 0; n < 4; n++) {
            of[n][0] *= cr0; of[n][1] *= cr0;
            of[n][2] *= cr1; of[n][3] *= cr1;
        }

        // ---- O += P @ V (expanded K'=192), warp slice 16 x 32 d-cols ----
        #pragma unroll
        for (int kk = 0; kk < 12; kk++) {
            unsigned a[4];
            ldsm_x4(a, aP + kk * 16);
            #pragma unroll
            for (int np = 0; np < 2; np++) {
                unsigned b[4];
                ldsm_x4(b, bV + np * 16 * SQ + kk * 16);
                mma16816(of[np * 2 + 0], a, &b[0]);
                mma16816(of[np * 2 + 1], a, &b[2]);
            }
        }
    }

    // ---- epilogue ----
    const float inv0 = 1.0f / l0s, inv1 = 1.0f / l1s;
    const int q0 = qb * 64 + wr * 16 + g;
    #pragma unroll
    for (int n = 0; n < 4; n++) {
        const int col = h * HDIM + wc * 32 + n * 8 + 2 * t;
        *(float2*)(g_att + (size_t)q0 * D_MODEL + col) =
            make_float2(of[n][0] * inv0, of[n][1] * inv0);
        *(float2*)(g_att + (size_t)(q0 + 8) * D_MODEL + col) =
            make_float2(of[n][2] * inv1, of[n][3] * inv1);
    }
}

// ---------------------------------------------------------------------------
extern "C" void kernel_launch(void* const* d_in, const int* in_sizes, int n_in,
                              void* d_out, int out_size)
{
    const float* x     = (const float*)d_in[0];
    const float* W_qkv = (const float*)d_in[1];
    const float* W_out = (const float*)d_in[2];
    const float* b_out = (const float*)d_in[3];
    float* out = (float*)d_out;

    float  *qkv, *att;
    __half *xe, *wqkve, *atte, *woute;
    cudaGetSymbolAddress((void**)&qkv,   g_qkv);
    cudaGetSymbolAddress((void**)&att,   g_att);
    cudaGetSymbolAddress((void**)&xe,    g_xe);
    cudaGetSymbolAddress((void**)&wqkve, g_wqkve);
    cudaGetSymbolAddress((void**)&atte,  g_atte);
    cudaGetSymbolAddress((void**)&woute, g_woute);

    const int ATTN_SMEM = 4 * 64 * SQ * 2 + 2 * 2 * 64 * 4;  // 103424 B
    cudaFuncSetAttribute(attn_kernel, cudaFuncAttributeMaxDynamicSharedMemorySize, ATTN_SMEM);

    // 1) expand x (A-pattern) and W_qkv (B-pattern, transposed)
    {
        int n = N_TOK * (D_MODEL / 4);
        expandA_kernel<<<(n + 255) / 256, 256>>>(x, xe, N_TOK, D_MODEL);
    }
    {
        int n = D_MODEL * QKV_N;
        expandBT_kernel<<<(n + 255) / 256, 256>>>(W_qkv, wqkve, D_MODEL, QKV_N);
    }
    // 2) QKV projection
    {
        dim3 grid(QKV_N / 128, N_TOK / 128);
        hgemm_kernel<false><<<grid, 256>>>(xe, wqkve, nullptr, qkv, N_TOK, QKV_N, K3_PROJ);
    }
    // 3) attention
    {
        dim3 grid(N_TOK / 64, H_HEADS);
        attn_kernel<<<grid, 256, ATTN_SMEM>>>();
    }
    // 4) expand att (A-pattern) and W_out (B-pattern, transposed)
    {
        int n = N_TOK * (D_MODEL / 4);
        expandA_kernel<<<(n + 255) / 256, 256>>>(att, atte, N_TOK, D_MODEL);
    }
    {
        int n = D_MODEL * D_MODEL;
        expandBT_kernel<<<(n + 255) / 256, 256>>>(W_out, woute, D_MODEL, D_MODEL);
    }
    // 5) output projection (+bias)
    {
        dim3 grid(D_MODEL / 128, N_TOK / 128);
        hgemm_kernel<true><<<grid, 256>>>(atte, woute, b_out, out, N_TOK, D_MODEL, K3_PROJ);
    }
}

// round 4
// speedup vs baseline: 1.3576x; 1.3576x over previous
#include <cuda_runtime.h>
#include <cuda_fp16.h>

// Problem constants (B=1)
#define N_TOK   4096
#define D_MODEL 768
#define H_HEADS 12
#define HDIM    64
#define QKV_N   2304
#define K3_PROJ 2304
#define ATT_SCALE 0.125f

// ---------------- scratch (device globals; no runtime allocation) ----------
__device__ float  g_qkv[N_TOK * QKV_N];
__device__ float  g_att[N_TOK * D_MODEL];
__device__ __half g_xe   [N_TOK  * K3_PROJ];
__device__ __half g_wqkve[QKV_N  * K3_PROJ];
__device__ __half g_atte [N_TOK  * K3_PROJ];
__device__ __half g_woute[D_MODEL* K3_PROJ];
// expanded attention operands (per head)
__device__ __half g_qe[H_HEADS * N_TOK * 192];   // [h][n][192] A-pattern, scaled
__device__ __half g_ke[H_HEADS * N_TOK * 192];   // [h][n][192] B-pattern
__device__ __half g_ve[H_HEADS * HDIM * 3 * N_TOK]; // [h][d][3n] B-pattern (transposed)

// ---------------- helpers ---------------------------------------------------
__device__ __forceinline__ void hsplit(float x, __half& h, __half& l) {
    h = __float2half_rn(x);
    l = __float2half_rn(x - __half2float(h));
}
__device__ __forceinline__ unsigned hpack(__half a, __half b) {
    __half2 h2 = __halves2half2(a, b);
    return *reinterpret_cast<unsigned*>(&h2);
}
__device__ __forceinline__ void mma16816(float c[4], const unsigned a[4], const unsigned b[2]) {
    asm volatile(
        "mma.sync.aligned.m16n8k16.row.col.f32.f16.f16.f32 "
        "{%0,%1,%2,%3}, {%4,%5,%6,%7}, {%8,%9}, {%0,%1,%2,%3};\n"
        : "+f"(c[0]), "+f"(c[1]), "+f"(c[2]), "+f"(c[3])
        : "r"(a[0]), "r"(a[1]), "r"(a[2]), "r"(a[3]), "r"(b[0]), "r"(b[1]));
}
__device__ __forceinline__ void ldsm_x4(unsigned r[4], const __half* p) {
    unsigned addr = (unsigned)__cvta_generic_to_shared(p);
    asm volatile("ldmatrix.sync.aligned.m8n8.x4.shared.b16 {%0,%1,%2,%3}, [%4];"
                 : "=r"(r[0]), "=r"(r[1]), "=r"(r[2]), "=r"(r[3]) : "r"(addr));
}
// swizzled smem offset: rows of 192 halfs, XOR at 8-half (16B) granularity
#define SW_OFF(row, col) ((row) * 192 + ((col) ^ (((row) & 7) << 3)))

// ---------------- expansion kernels (projections) ---------------------------
__global__ void expandA_kernel(const float* __restrict__ X, __half* __restrict__ Xe,
                               int M, int K)
{
    const int kq = K >> 2;
    int idx = blockIdx.x * blockDim.x + threadIdx.x;
    if (idx >= M * kq) return;
    int m = idx / kq;
    int k0 = (idx - m * kq) * 4;
    float4 v = *(const float4*)(X + (size_t)m * K + k0);
    __half h0,l0,h1,l1,h2,l2,h3,l3;
    hsplit(v.x,h0,l0); hsplit(v.y,h1,l1); hsplit(v.z,h2,l2); hsplit(v.w,h3,l3);
    unsigned* o = (unsigned*)(Xe + (size_t)m * 3 * K + 3 * k0);
    o[0]=hpack(h0,h0); o[1]=hpack(l0,h1); o[2]=hpack(h1,l1);
    o[3]=hpack(h2,h2); o[4]=hpack(l2,h3); o[5]=hpack(h3,l3);
}
__global__ void expandBT_kernel(const float* __restrict__ W, __half* __restrict__ We,
                                int K, int N)
{
    int idx = blockIdx.x * blockDim.x + threadIdx.x;
    if (idx >= K * N) return;
    int k = idx / N, n = idx - k * N;
    float x = W[(size_t)k * N + n];
    __half h, l; hsplit(x, h, l);
    __half* o = We + (size_t)n * 3 * K + 3 * k;
    o[0] = h; o[1] = l; o[2] = h;
}

// ---------------- attention operand expansion (once, out of loop) -----------
// thread handles (n, h, c): 16 headdim elements of Q, K, V each.
__global__ void expand_attn_kernel()
{
    int idx = blockIdx.x * blockDim.x + threadIdx.x;
    if (idx >= N_TOK * H_HEADS * 4) return;
    const int c  = idx & 3;
    const int h  = (idx >> 2) & 15;        // H=12 < 16; guard below
    const int n  = idx / (4 * H_HEADS);
    if (((idx >> 2) % H_HEADS) != h) { /* unreachable for h<12 */ }
    const int hh = (idx >> 2) % H_HEADS;
    const int d0 = c * 16;

    const float* base = g_qkv + (size_t)n * QKV_N + hh * HDIM + d0;

    // Q: A-pattern {hi,hi,lo}, pre-scaled
    {
        unsigned* dst = (unsigned*)(g_qe + ((size_t)hh * N_TOK + n) * 192 + 3 * d0);
        #pragma unroll
        for (int i = 0; i < 4; i++) {
            float4 v = *(const float4*)(base + i * 4);
            __half h0,l0,h1,l1,h2,l2,h3,l3;
            hsplit(v.x * ATT_SCALE, h0,l0); hsplit(v.y * ATT_SCALE, h1,l1);
            hsplit(v.z * ATT_SCALE, h2,l2); hsplit(v.w * ATT_SCALE, h3,l3);
            dst[i*6+0]=hpack(h0,h0); dst[i*6+1]=hpack(l0,h1); dst[i*6+2]=hpack(h1,l1);
            dst[i*6+3]=hpack(h2,h2); dst[i*6+4]=hpack(l2,h3); dst[i*6+5]=hpack(h3,l3);
        }
    }
    // K: B-pattern {hi,lo,hi}
    {
        const float* kp = base + D_MODEL;
        unsigned* dst = (unsigned*)(g_ke + ((size_t)hh * N_TOK + n) * 192 + 3 * d0);
        #pragma unroll
        for (int i = 0; i < 4; i++) {
            float4 v = *(const float4*)(kp + i * 4);
            __half h0,l0,h1,l1,h2,l2,h3,l3;
            hsplit(v.x,h0,l0); hsplit(v.y,h1,l1); hsplit(v.z,h2,l2); hsplit(v.w,h3,l3);
            dst[i*6+0]=hpack(h0,l0); dst[i*6+1]=hpack(h0,h1); dst[i*6+2]=hpack(l1,h1);
            dst[i*6+3]=hpack(h2,l2); dst[i*6+4]=hpack(h2,h3); dst[i*6+5]=hpack(l3,h3);
        }
    }
    // V: transposed d-major, B-pattern {hi,lo,hi} along n
    {
        const float* vp = base + 2 * D_MODEL;
        #pragma unroll
        for (int i = 0; i < 4; i++) {
            float4 v = *(const float4*)(vp + i * 4);
            float va[4] = {v.x, v.y, v.z, v.w};
            #pragma unroll
            for (int e = 0; e < 4; e++) {
                __half hh2, ll; hsplit(va[e], hh2, ll);
                __half* o = g_ve + ((size_t)hh * HDIM + d0 + i * 4 + e) * (3 * N_TOK) + 3 * n;
                o[0] = hh2; o[1] = ll; o[2] = hh2;
            }
        }
    }
}

// ---------------- HGEMM (unchanged from R3) ----------------------------------
template <bool HAS_BIAS>
__global__ __launch_bounds__(256)
void hgemm_kernel(const __half* __restrict__ A, const __half* __restrict__ Bt,
                  const float* __restrict__ bias, float* __restrict__ C,
                  int M, int N, int K3)
{
    constexpr int LDSH = 72;
    __shared__ __align__(16) __half As[128 * LDSH];
    __shared__ __align__(16) __half Bs[128 * LDSH];

    const int tid = threadIdx.x, wid = tid >> 5, lane = tid & 31;
    const int g = lane >> 2, t = lane & 3;
    const int wm = wid & 3, wn = wid >> 2;
    const int m0 = blockIdx.y * 128, n0 = blockIdx.x * 128;
    const int NT = K3 >> 6;

    const __half* Ab = A  + (size_t)m0 * K3;
    const __half* Bb = Bt + (size_t)n0 * K3;

    const int ld_row = tid >> 3;
    const int ld_c16 = (tid & 7) * 8;

    const __half* aA = As + (wm * 32 + (lane & 15)) * LDSH + (lane >> 4) * 8;
    const __half* bB = Bs + (wn * 64 + ((lane >> 4) << 3) + (lane & 7)) * LDSH
                          + ((lane >> 3) & 1) * 8;

    uint4 ra[4], rb[4];
    #pragma unroll
    for (int i = 0; i < 4; i++) {
        int row = ld_row + i * 32;
        ra[i] = *(const uint4*)(Ab + (size_t)row * K3 + ld_c16);
        rb[i] = *(const uint4*)(Bb + (size_t)row * K3 + ld_c16);
    }
    #pragma unroll
    for (int i = 0; i < 4; i++) {
        int row = ld_row + i * 32;
        *(uint4*)(As + row * LDSH + ld_c16) = ra[i];
        *(uint4*)(Bs + row * LDSH + ld_c16) = rb[i];
    }
    __syncthreads();

    float cf[2][8][4] = {};

    for (int kt = 0; kt < NT; kt++) {
        if (kt + 1 < NT) {
            #pragma unroll
            for (int i = 0; i < 4; i++) {
                int row = ld_row + i * 32;
                ra[i] = *(const uint4*)(Ab + (size_t)row * K3 + (kt + 1) * 64 + ld_c16);
                rb[i] = *(const uint4*)(Bb + (size_t)row * K3 + (kt + 1) * 64 + ld_c16);
            }
        }
        #pragma unroll
        for (int kk = 0; kk < 4; kk++) {
            unsigned af[2][4], bf[4][4];
            #pragma unroll
            for (int mi = 0; mi < 2; mi++)
                ldsm_x4(af[mi], aA + mi * 16 * LDSH + kk * 16);
            #pragma unroll
            for (int np = 0; np < 4; np++)
                ldsm_x4(bf[np], bB + np * 16 * LDSH + kk * 16);
            #pragma unroll
            for (int mi = 0; mi < 2; mi++)
                #pragma unroll
                for (int ni = 0; ni < 8; ni++)
                    mma16816(cf[mi][ni], af[mi], &bf[ni >> 1][(ni & 1) * 2]);
        }
        __syncthreads();
        if (kt + 1 < NT) {
            #pragma unroll
            for (int i = 0; i < 4; i++) {
                int row = ld_row + i * 32;
                *(uint4*)(As + row * LDSH + ld_c16) = ra[i];
                *(uint4*)(Bs + row * LDSH + ld_c16) = rb[i];
            }
            __syncthreads();
        }
    }

    #pragma unroll
    for (int mi = 0; mi < 2; mi++) {
        const int r0 = m0 + wm * 32 + mi * 16 + g;
        #pragma unroll
        for (int ni = 0; ni < 8; ni++) {
            const int col = n0 + wn * 64 + ni * 8 + 2 * t;
            float bv0 = 0.f, bv1 = 0.f;
            if (HAS_BIAS) { bv0 = bias[col]; bv1 = bias[col + 1]; }
            *(float2*)(C + (size_t)r0 * N + col) =
                make_float2(cf[mi][ni][0] + bv0, cf[mi][ni][1] + bv1);
            *(float2*)(C + (size_t)(r0 + 8) * N + col) =
                make_float2(cf[mi][ni][2] + bv0, cf[mi][ni][3] + bv1);
        }
    }
}

// ---------------- Flash attention: precomputed operands, Br=64, 4 warps -----
// warp = 16 q-rows x 64 keys; warp-local softmax; Q frags in registers.
// smem = 3 x 64 x 192 halfs (XOR-swizzled) = 72 KB -> 3 CTAs/SM.
__global__ __launch_bounds__(128, 3)
void attn_kernel()
{
    extern __shared__ __align__(16) __half sm[];
    __half* Ke = sm;                 // [64][192] swizzled
    __half* Ve = Ke + 64 * 192;      // [64][192] swizzled (d-major)
    __half* Pe = Ve + 64 * 192;      // [64][192] swizzled (also Q staging)

    const int qb = blockIdx.x, h = blockIdx.y;
    const int tid = threadIdx.x, wid = tid >> 5, lane = tid & 31;
    const int g = lane >> 2, t = lane & 3;

    // ---- stage Q tile into Pe, then preload fragments into registers ----
    {
        const __half* src = g_qe + ((size_t)h * N_TOK + qb * 64) * 192;
        #pragma unroll
        for (int it = 0; it < 12; it++) {
            int j = tid + it * 128;
            int r = j / 24, cj = (j % 24) * 8;
            uint4 v = *(const uint4*)(src + (size_t)r * 192 + cj);
            *(uint4*)(Pe + SW_OFF(r, cj)) = v;
        }
    }
    __syncthreads();

    const int ra = wid * 16 + (lane & 15);
    const int xa = (ra & 7) << 3;
    const int ca = (lane >> 4) * 8;
    unsigned qf[12][4];
    #pragma unroll
    for (int kk = 0; kk < 12; kk++)
        ldsm_x4(qf[kk], Pe + ra * 192 + ((kk * 16 + ca) ^ xa));

    const int rb = ((lane >> 4) << 3) + (lane & 7);
    const int xb = (rb & 7) << 3;
    const int cb = ((lane >> 3) & 1) * 8;

    float of[8][4] = {};
    float m0 = -1e30f, m1 = -1e30f, l0s = 0.f, l1s = 0.f;
    const int r0 = wid * 16 + g;
    const int xp = (r0 & 7) << 3;

    const __half* keg = g_ke + (size_t)h * N_TOK * 192;
    const __half* veg = g_ve + (size_t)h * HDIM * (3 * N_TOK);

    for (int kb = 0; kb < N_TOK / 64; kb++) {
        __syncthreads();   // prior iter's ldsm reads of Ke/Ve done; Pe(Q) reads done
        // ---- copy K and V tiles (swizzled stores) ----
        {
            const __half* ks = keg + (size_t)(kb * 64) * 192;
            #pragma unroll
            for (int it = 0; it < 12; it++) {
                int j = tid + it * 128;
                int r = j / 24, cj = (j % 24) * 8;
                uint4 v = *(const uint4*)(ks + (size_t)r * 192 + cj);
                *(uint4*)(Ke + SW_OFF(r, cj)) = v;
            }
            #pragma unroll
            for (int it = 0; it < 12; it++) {
                int j = tid + it * 128;
                int r = j / 24, cj = (j % 24) * 8;
                uint4 v = *(const uint4*)(veg + (size_t)r * (3 * N_TOK) + kb * 192 + cj);
                *(uint4*)(Ve + SW_OFF(r, cj)) = v;
            }
        }
        __syncthreads();

        // ---- S = Q @ K^T (expanded K'=192) ----
        float sf[8][4] = {};
        #pragma unroll
        for (int kk = 0; kk < 12; kk++) {
            #pragma unroll
            for (int np = 0; np < 4; np++) {
                unsigned b[4];
                ldsm_x4(b, Ke + (rb + np * 16) * 192 + ((kk * 16 + cb) ^ xb));
                mma16816(sf[np * 2 + 0], qf[kk], &b[0]);
                mma16816(sf[np * 2 + 1], qf[kk], &b[2]);
            }
        }

        // ---- warp-local online softmax ----
        float mx0 = -1e30f, mx1 = -1e30f;
        #pragma unroll
        for (int n = 0; n < 8; n++) {
            mx0 = fmaxf(mx0, fmaxf(sf[n][0], sf[n][1]));
            mx1 = fmaxf(mx1, fmaxf(sf[n][2], sf[n][3]));
        }
        mx0 = fmaxf(mx0, __shfl_xor_sync(0xffffffffu, mx0, 1));
        mx0 = fmaxf(mx0, __shfl_xor_sync(0xffffffffu, mx0, 2));
        mx1 = fmaxf(mx1, __shfl_xor_sync(0xffffffffu, mx1, 1));
        mx1 = fmaxf(mx1, __shfl_xor_sync(0xffffffffu, mx1, 2));

        const float mn0 = fmaxf(m0, mx0), mn1 = fmaxf(m1, mx1);
        const float cr0 = __expf(m0 - mn0), cr1 = __expf(m1 - mn1);
        float rs0 = 0.f, rs1 = 0.f;

        __half* prow0 = Pe + (size_t)r0 * 192;
        __half* prow1 = prow0 + 8 * 192;
        #pragma unroll
        for (int n = 0; n < 8; n++) {
            float p00 = __expf(sf[n][0] - mn0);
            float p01 = __expf(sf[n][1] - mn0);
            float p10 = __expf(sf[n][2] - mn1);
            float p11 = __expf(sf[n][3] - mn1);
            rs0 += p00 + p01;
            rs1 += p10 + p11;
            const int c0 = 3 * (n * 8 + 2 * t);   // even -> u32-aligned, granule-safe
            __half a0,b0,a1,b1;
            hsplit(p00, a0, b0); hsplit(p01, a1, b1);
            *(unsigned*)(prow0 + ((c0 + 0) ^ xp)) = hpack(a0, a0);
            *(unsigned*)(prow0 + ((c0 + 2) ^ xp)) = hpack(b0, a1);
            *(unsigned*)(prow0 + ((c0 + 4) ^ xp)) = hpack(a1, b1);
            hsplit(p10, a0, b0); hsplit(p11, a1, b1);
            *(unsigned*)(prow1 + ((c0 + 0) ^ xp)) = hpack(a0, a0);
            *(unsigned*)(prow1 + ((c0 + 2) ^ xp)) = hpack(b0, a1);
            *(unsigned*)(prow1 + ((c0 + 4) ^ xp)) = hpack(a1, b1);
        }
        rs0 += __shfl_xor_sync(0xffffffffu, rs0, 1);
        rs0 += __shfl_xor_sync(0xffffffffu, rs0, 2);
        rs1 += __shfl_xor_sync(0xffffffffu, rs1, 1);
        rs1 += __shfl_xor_sync(0xffffffffu, rs1, 2);

        l0s = l0s * cr0 + rs0;  m0 = mn0;
        l1s = l1s * cr1 + rs1;  m1 = mn1;
        #pragma unroll
        for (int n = 0; n < 8; n++) {
            of[n][0] *= cr0; of[n][1] *= cr0;
            of[n][2] *= cr1; of[n][3] *= cr1;
        }
        __syncwarp();   // Pe rows are warp-local: order STS before LDSM

        // ---- O += P @ V (expanded K'=192) ----
        #pragma unroll
        for (int kk = 0; kk < 12; kk++) {
            unsigned a[4];
            ldsm_x4(a, Pe + ra * 192 + ((kk * 16 + ca) ^ xa));
            #pragma unroll
            for (int np = 0; np < 4; np++) {
                unsigned b[4];
                ldsm_x4(b, Ve + (rb + np * 16) * 192 + ((kk * 16 + cb) ^ xb));
                mma16816(of[np * 2 + 0], a, &b[0]);
                mma16816(of[np * 2 + 1], a, &b[2]);
            }
        }
    }

    // ---- epilogue ----
    const float inv0 = 1.0f / l0s, inv1 = 1.0f / l1s;
    const int q0 = qb * 64 + wid * 16 + g;
    #pragma unroll
    for (int n = 0; n < 8; n++) {
        const int col = h * HDIM + n * 8 + 2 * t;
        *(float2*)(g_att + (size_t)q0 * D_MODEL + col) =
            make_float2(of[n][0] * inv0, of[n][1] * inv0);
        *(float2*)(g_att + (size_t)(q0 + 8) * D_MODEL + col) =
            make_float2(of[n][2] * inv1, of[n][3] * inv1);
    }
}

// ---------------------------------------------------------------------------
extern "C" void kernel_launch(void* const* d_in, const int* in_sizes, int n_in,
                              void* d_out, int out_size)
{
    const float* x     = (const float*)d_in[0];
    const float* W_qkv = (const float*)d_in[1];
    const float* W_out = (const float*)d_in[2];
    const float* b_out = (const float*)d_in[3];
    float* out = (float*)d_out;

    float  *qkv, *att;
    __half *xe, *wqkve, *atte, *woute;
    cudaGetSymbolAddress((void**)&qkv,   g_qkv);
    cudaGetSymbolAddress((void**)&att,   g_att);
    cudaGetSymbolAddress((void**)&xe,    g_xe);
    cudaGetSymbolAddress((void**)&wqkve, g_wqkve);
    cudaGetSymbolAddress((void**)&atte,  g_atte);
    cudaGetSymbolAddress((void**)&woute, g_woute);

    const int ATTN_SMEM = 3 * 64 * 192 * 2;   // 73728 B
    cudaFuncSetAttribute(attn_kernel, cudaFuncAttributeMaxDynamicSharedMemorySize, ATTN_SMEM);

    // 1) expand x / W_qkv for the QKV projection
    {
        int n = N_TOK * (D_MODEL / 4);
        expandA_kernel<<<(n + 255) / 256, 256>>>(x, xe, N_TOK, D_MODEL);
    }
    {
        int n = D_MODEL * QKV_N;
        expandBT_kernel<<<(n + 255) / 256, 256>>>(W_qkv, wqkve, D_MODEL, QKV_N);
    }
    // 2) QKV projection -> g_qkv (fp32)
    {
        dim3 grid(QKV_N / 128, N_TOK / 128);
        hgemm_kernel<false><<<grid, 256>>>(xe, wqkve, nullptr, qkv, N_TOK, QKV_N, K3_PROJ);
    }
    // 3) one-shot expansion of Q/K/V attention operands
    {
        int n = N_TOK * H_HEADS * 4;
        expand_attn_kernel<<<(n + 255) / 256, 256>>>();
    }
    // 4) attention
    {
        dim3 grid(N_TOK / 64, H_HEADS);
        attn_kernel<<<grid, 128, ATTN_SMEM>>>();
    }
    // 5) expand att / W_out, output projection (+bias)
    {
        int n = N_TOK * (D_MODEL / 4);
        expandA_kernel<<<(n + 255) / 256, 256>>>(att, atte, N_TOK, D_MODEL);
    }
    {
        int n = D_MODEL * D_MODEL;
        expandBT_kernel<<<(n + 255) / 256, 256>>>(W_out, woute, D_MODEL, D_MODEL);
    }
    {
        dim3 grid(D_MODEL / 128, N_TOK / 128);
        hgemm_kernel<true><<<grid, 256>>>(atte, woute, b_out, out, N_TOK, D_MODEL, K3_PROJ);
    }
}

// round 5
// speedup vs baseline: 1.5515x; 1.1428x over previous
#include <cuda_runtime.h>
#include <cuda_fp16.h>

// Problem constants (B=1)
#define N_TOK   4096
#define D_MODEL 768
#define H_HEADS 12
#define HDIM    64
#define QKV_N   2304
#define K3_PROJ 2304
#define ATT_SCALE 0.125f

// ---------------- scratch (device globals; no runtime allocation) ----------
__device__ __align__(16) __half g_xe   [N_TOK  * K3_PROJ];
__device__ __align__(16) __half g_wqkve[QKV_N  * K3_PROJ];
__device__ __align__(16) __half g_atte [N_TOK  * K3_PROJ];
__device__ __align__(16) __half g_woute[D_MODEL* K3_PROJ];
// expanded attention operands (per head)
__device__ __align__(16) __half g_qe [H_HEADS * N_TOK * 192];      // [h][n][192] A-pattern, scaled
__device__ __align__(16) __half g_ke [H_HEADS * N_TOK * 192];      // [h][n][192] B-pattern
__device__ __align__(16) __half g_vte[H_HEADS * 3 * N_TOK * HDIM]; // [h][3n+r][d] row-replicated B-pattern

// ---------------- helpers ---------------------------------------------------
__device__ __forceinline__ void hsplit(float x, __half& h, __half& l) {
    h = __float2half_rn(x);
    l = __float2half_rn(x - __half2float(h));
}
__device__ __forceinline__ unsigned hpack(__half a, __half b) {
    __half2 h2 = __halves2half2(a, b);
    return *reinterpret_cast<unsigned*>(&h2);
}
__device__ __forceinline__ void mma16816(float c[4], const unsigned a[4], const unsigned b[2]) {
    asm volatile(
        "mma.sync.aligned.m16n8k16.row.col.f32.f16.f16.f32 "
        "{%0,%1,%2,%3}, {%4,%5,%6,%7}, {%8,%9}, {%0,%1,%2,%3};\n"
        : "+f"(c[0]), "+f"(c[1]), "+f"(c[2]), "+f"(c[3])
        : "r"(a[0]), "r"(a[1]), "r"(a[2]), "r"(a[3]), "r"(b[0]), "r"(b[1]));
}
__device__ __forceinline__ void ldsm_x4(unsigned r[4], const __half* p) {
    unsigned addr = (unsigned)__cvta_generic_to_shared(p);
    asm volatile("ldmatrix.sync.aligned.m8n8.x4.shared.b16 {%0,%1,%2,%3}, [%4];"
                 : "=r"(r[0]), "=r"(r[1]), "=r"(r[2]), "=r"(r[3]) : "r"(addr));
}
__device__ __forceinline__ void ldsm_x4_trans(unsigned r[4], const __half* p) {
    unsigned addr = (unsigned)__cvta_generic_to_shared(p);
    asm volatile("ldmatrix.sync.aligned.m8n8.x4.trans.shared.b16 {%0,%1,%2,%3}, [%4];"
                 : "=r"(r[0]), "=r"(r[1]), "=r"(r[2]), "=r"(r[3]) : "r"(addr));
}
// swizzles: XOR at 8-half (16B) granularity
#define SW_OFF(row, col) ((row) * 192 + ((col) ^ (((row) & 7) << 3)))   // 192-half rows
#define SWV(row, col)    ((row) * 64  + ((col) ^ (((row) & 7) << 3)))   // 64-half rows

// ---------------- input expansion kernels ------------------------------------
__global__ void expandA_kernel(const float* __restrict__ X, __half* __restrict__ Xe,
                               int M, int K)
{
    const int kq = K >> 2;
    int idx = blockIdx.x * blockDim.x + threadIdx.x;
    if (idx >= M * kq) return;
    int m = idx / kq;
    int k0 = (idx - m * kq) * 4;
    float4 v = *(const float4*)(X + (size_t)m * K + k0);
    __half h0,l0,h1,l1,h2,l2,h3,l3;
    hsplit(v.x,h0,l0); hsplit(v.y,h1,l1); hsplit(v.z,h2,l2); hsplit(v.w,h3,l3);
    unsigned* o = (unsigned*)(Xe + (size_t)m * 3 * K + 3 * k0);
    o[0]=hpack(h0,h0); o[1]=hpack(l0,h1); o[2]=hpack(h1,l1);
    o[3]=hpack(h2,h2); o[4]=hpack(l2,h3); o[5]=hpack(h3,l3);
}
__global__ void expandBT_kernel(const float* __restrict__ W, __half* __restrict__ We,
                                int K, int N)
{
    int idx = blockIdx.x * blockDim.x + threadIdx.x;
    if (idx >= K * N) return;
    int k = idx / N, n = idx - k * N;
    float x = W[(size_t)k * N + n];
    __half h, l; hsplit(x, h, l);
    __half* o = We + (size_t)n * 3 * K + 3 * k;
    o[0] = h; o[1] = l; o[2] = h;
}

// ---------------- HGEMM with fused epilogues ---------------------------------
// EPI 0: QKV — write expanded g_qe/g_ke/g_vte directly.
// EPI 1: OUT — fp32 + bias to C.
template <int EPI>
__global__ __launch_bounds__(256)
void hgemm_kernel(const __half* __restrict__ A, const __half* __restrict__ Bt,
                  const float* __restrict__ bias, float* __restrict__ C,
                  int M, int N, int K3)
{
    constexpr int LDSH = 72;
    __shared__ __align__(16) __half As[128 * LDSH];
    __shared__ __align__(16) __half Bs[128 * LDSH];

    const int tid = threadIdx.x, wid = tid >> 5, lane = tid & 31;
    const int g = lane >> 2, t = lane & 3;
    const int wm = wid & 3, wn = wid >> 2;
    const int m0 = blockIdx.y * 128, n0 = blockIdx.x * 128;
    const int NT = K3 >> 6;

    const __half* Ab = A  + (size_t)m0 * K3;
    const __half* Bb = Bt + (size_t)n0 * K3;

    const int ld_row = tid >> 3;
    const int ld_c16 = (tid & 7) * 8;

    const __half* aA = As + (wm * 32 + (lane & 15)) * LDSH + (lane >> 4) * 8;
    const __half* bB = Bs + (wn * 64 + ((lane >> 4) << 3) + (lane & 7)) * LDSH
                          + ((lane >> 3) & 1) * 8;

    uint4 ra[4], rb[4];
    #pragma unroll
    for (int i = 0; i < 4; i++) {
        int row = ld_row + i * 32;
        ra[i] = *(const uint4*)(Ab + (size_t)row * K3 + ld_c16);
        rb[i] = *(const uint4*)(Bb + (size_t)row * K3 + ld_c16);
    }
    #pragma unroll
    for (int i = 0; i < 4; i++) {
        int row = ld_row + i * 32;
        *(uint4*)(As + row * LDSH + ld_c16) = ra[i];
        *(uint4*)(Bs + row * LDSH + ld_c16) = rb[i];
    }
    __syncthreads();

    float cf[2][8][4] = {};

    for (int kt = 0; kt < NT; kt++) {
        if (kt + 1 < NT) {
            #pragma unroll
            for (int i = 0; i < 4; i++) {
                int row = ld_row + i * 32;
                ra[i] = *(const uint4*)(Ab + (size_t)row * K3 + (kt + 1) * 64 + ld_c16);
                rb[i] = *(const uint4*)(Bb + (size_t)row * K3 + (kt + 1) * 64 + ld_c16);
            }
        }
        #pragma unroll
        for (int kk = 0; kk < 4; kk++) {
            unsigned af[2][4], bf[4][4];
            #pragma unroll
            for (int mi = 0; mi < 2; mi++)
                ldsm_x4(af[mi], aA + mi * 16 * LDSH + kk * 16);
            #pragma unroll
            for (int np = 0; np < 4; np++)
                ldsm_x4(bf[np], bB + np * 16 * LDSH + kk * 16);
            #pragma unroll
            for (int mi = 0; mi < 2; mi++)
                #pragma unroll
                for (int ni = 0; ni < 8; ni++)
                    mma16816(cf[mi][ni], af[mi], &bf[ni >> 1][(ni & 1) * 2]);
        }
        __syncthreads();
        if (kt + 1 < NT) {
            #pragma unroll
            for (int i = 0; i < 4; i++) {
                int row = ld_row + i * 32;
                *(uint4*)(As + row * LDSH + ld_c16) = ra[i];
                *(uint4*)(Bs + row * LDSH + ld_c16) = rb[i];
            }
            __syncthreads();
        }
    }

    #pragma unroll
    for (int mi = 0; mi < 2; mi++) {
        const int r0 = m0 + wm * 32 + mi * 16 + g;
        #pragma unroll
        for (int ni = 0; ni < 8; ni++) {
            const int col = n0 + wn * 64 + ni * 8 + 2 * t;
            #pragma unroll
            for (int rr = 0; rr < 2; rr++) {
                const int row = r0 + rr * 8;
                const float v0 = cf[mi][ni][rr * 2 + 0];
                const float v1 = cf[mi][ni][rr * 2 + 1];
                if (EPI == 0) {
                    if (col < 768) {            // Q: A-pattern, pre-scaled
                        const int hh = col >> 6, d = col & 63;
                        __half h0,l0,h1,l1;
                        hsplit(v0 * ATT_SCALE, h0, l0);
                        hsplit(v1 * ATT_SCALE, h1, l1);
                        unsigned* dst = (unsigned*)(g_qe + ((size_t)hh * N_TOK + row) * 192 + 3 * d);
                        dst[0]=hpack(h0,h0); dst[1]=hpack(l0,h1); dst[2]=hpack(h1,l1);
                    } else if (col < 1536) {    // K: B-pattern
                        const int cc = col - 768, hh = cc >> 6, d = cc & 63;
                        __half h0,l0,h1,l1;
                        hsplit(v0, h0, l0); hsplit(v1, h1, l1);
                        unsigned* dst = (unsigned*)(g_ke + ((size_t)hh * N_TOK + row) * 192 + 3 * d);
                        dst[0]=hpack(h0,l0); dst[1]=hpack(h0,h1); dst[2]=hpack(l1,h1);
                    } else {                    // V: row-replicated B-pattern [3n][d]
                        const int cc = col - 1536, hh = cc >> 6, d = cc & 63;
                        __half h0,l0,h1,l1;
                        hsplit(v0, h0, l0); hsplit(v1, h1, l1);
                        __half* base = g_vte + (size_t)hh * (3 * N_TOK * HDIM)
                                             + (size_t)(3 * row) * HDIM + d;
                        *(unsigned*)(base)            = hpack(h0, h1);
                        *(unsigned*)(base + HDIM)     = hpack(l0, l1);
                        *(unsigned*)(base + 2 * HDIM) = hpack(h0, h1);
                    }
                } else {
                    const float bv0 = bias[col], bv1 = bias[col + 1];
                    *(float2*)(C + (size_t)row * N + col) = make_float2(v0 + bv0, v1 + bv1);
                }
            }
        }
    }
}

// ---------------- Flash attention: precomputed operands, Br=64, 4 warps -----
// warp = 16 q-rows x 64 keys; warp-local softmax; Q frags in registers.
// smem = Ke[64][192] + Vt[192][64] + Pe[64][192] = 72 KB -> 3 CTAs/SM.
__global__ __launch_bounds__(128, 3)
void attn_kernel()
{
    extern __shared__ __align__(16) __half sm[];
    __half* Ke = sm;                 // [64][192] swizzled (key rows, B-pattern)
    __half* Vt = Ke + 64 * 192;      // [192][64] swizzled (expanded-key rows)
    __half* Pe = Vt + 192 * 64;      // [64][192] swizzled (P; also Q staging)

    const int qb = blockIdx.x, h = blockIdx.y;
    const int tid = threadIdx.x, wid = tid >> 5, lane = tid & 31;
    const int g = lane >> 2, t = lane & 3;

    // ---- stage Q tile into Pe, preload fragments into registers ----
    {
        const __half* src = g_qe + ((size_t)h * N_TOK + qb * 64) * 192;
        #pragma unroll
        for (int it = 0; it < 12; it++) {
            int j = tid + it * 128;
            int r = j / 24, cj = (j % 24) * 8;
            uint4 v = *(const uint4*)(src + (size_t)r * 192 + cj);
            *(uint4*)(Pe + SW_OFF(r, cj)) = v;
        }
    }
    __syncthreads();

    const int ra = wid * 16 + (lane & 15);
    const int xa = (ra & 7) << 3;
    const int ca = (lane >> 4) * 8;
    unsigned qf[12][4];
    #pragma unroll
    for (int kk = 0; kk < 12; kk++)
        ldsm_x4(qf[kk], Pe + ra * 192 + ((kk * 16 + ca) ^ xa));

    const int rb = ((lane >> 4) << 3) + (lane & 7);   // K-tile row (key)
    const int xb = (rb & 7) << 3;
    const int cb = ((lane >> 3) & 1) * 8;

    const int rv = lane & 15;                          // Vt row-within-chunk
    const int cv = (lane >> 4) * 8;                    // Vt col offset

    float of[8][4] = {};
    float m0 = -1e30f, m1 = -1e30f, l0s = 0.f, l1s = 0.f;
    const int r0 = wid * 16 + g;
    const int xp = (r0 & 7) << 3;

    const __half* keg = g_ke  + (size_t)h * N_TOK * 192;
    const __half* vtg = g_vte + (size_t)h * (3 * N_TOK * HDIM);

    for (int kb = 0; kb < N_TOK / 64; kb++) {
        __syncthreads();
        // ---- copy K tile [64][192] and Vt tile [192][64] (swizzled stores) ----
        {
            const __half* ks = keg + (size_t)(kb * 64) * 192;
            #pragma unroll
            for (int it = 0; it < 12; it++) {
                int j = tid + it * 128;
                int r = j / 24, cj = (j % 24) * 8;
                uint4 v = *(const uint4*)(ks + (size_t)r * 192 + cj);
                *(uint4*)(Ke + SW_OFF(r, cj)) = v;
            }
            const __half* vs = vtg + (size_t)(kb * 192) * HDIM;
            #pragma unroll
            for (int it = 0; it < 12; it++) {
                int j = tid + it * 128;
                int r = j >> 3, cj = (j & 7) * 8;
                uint4 v = *(const uint4*)(vs + (size_t)r * HDIM + cj);
                *(uint4*)(Vt + SWV(r, cj)) = v;
            }
        }
        __syncthreads();

        // ---- S = Q @ K^T (expanded K'=192) ----
        float sf[8][4] = {};
        #pragma unroll
        for (int kk = 0; kk < 12; kk++) {
            #pragma unroll
            for (int np = 0; np < 4; np++) {
                unsigned b[4];
                ldsm_x4(b, Ke + (rb + np * 16) * 192 + ((kk * 16 + cb) ^ xb));
                mma16816(sf[np * 2 + 0], qf[kk], &b[0]);
                mma16816(sf[np * 2 + 1], qf[kk], &b[2]);
            }
        }

        // ---- warp-local online softmax ----
        float mx0 = -1e30f, mx1 = -1e30f;
        #pragma unroll
        for (int n = 0; n < 8; n++) {
            mx0 = fmaxf(mx0, fmaxf(sf[n][0], sf[n][1]));
            mx1 = fmaxf(mx1, fmaxf(sf[n][2], sf[n][3]));
        }
        mx0 = fmaxf(mx0, __shfl_xor_sync(0xffffffffu, mx0, 1));
        mx0 = fmaxf(mx0, __shfl_xor_sync(0xffffffffu, mx0, 2));
        mx1 = fmaxf(mx1, __shfl_xor_sync(0xffffffffu, mx1, 1));
        mx1 = fmaxf(mx1, __shfl_xor_sync(0xffffffffu, mx1, 2));

        const float mn0 = fmaxf(m0, mx0), mn1 = fmaxf(m1, mx1);
        const float cr0 = __expf(m0 - mn0), cr1 = __expf(m1 - mn1);
        float rs0 = 0.f, rs1 = 0.f;

        __half* prow0 = Pe + (size_t)r0 * 192;
        __half* prow1 = prow0 + 8 * 192;
        #pragma unroll
        for (int n = 0; n < 8; n++) {
            float p00 = __expf(sf[n][0] - mn0);
            float p01 = __expf(sf[n][1] - mn0);
            float p10 = __expf(sf[n][2] - mn1);
            float p11 = __expf(sf[n][3] - mn1);
            rs0 += p00 + p01;
            rs1 += p10 + p11;
            const int c0 = 3 * (n * 8 + 2 * t);
            __half a0,b0,a1,b1;
            hsplit(p00, a0, b0); hsplit(p01, a1, b1);
            *(unsigned*)(prow0 + ((c0 + 0) ^ xp)) = hpack(a0, a0);
            *(unsigned*)(prow0 + ((c0 + 2) ^ xp)) = hpack(b0, a1);
            *(unsigned*)(prow0 + ((c0 + 4) ^ xp)) = hpack(a1, b1);
            hsplit(p10, a0, b0); hsplit(p11, a1, b1);
            *(unsigned*)(prow1 + ((c0 + 0) ^ xp)) = hpack(a0, a0);
            *(unsigned*)(prow1 + ((c0 + 2) ^ xp)) = hpack(b0, a1);
            *(unsigned*)(prow1 + ((c0 + 4) ^ xp)) = hpack(a1, b1);
        }
        rs0 += __shfl_xor_sync(0xffffffffu, rs0, 1);
        rs0 += __shfl_xor_sync(0xffffffffu, rs0, 2);
        rs1 += __shfl_xor_sync(0xffffffffu, rs1, 1);
        rs1 += __shfl_xor_sync(0xffffffffu, rs1, 2);

        l0s = l0s * cr0 + rs0;  m0 = mn0;
        l1s = l1s * cr1 + rs1;  m1 = mn1;
        #pragma unroll
        for (int n = 0; n < 8; n++) {
            of[n][0] *= cr0; of[n][1] *= cr0;
            of[n][2] *= cr1; of[n][3] *= cr1;
        }
        __syncwarp();   // Pe rows are warp-local: order STS before LDSM

        // ---- O += P @ V (expanded K'=192), V via ldmatrix.trans ----
        #pragma unroll
        for (int kk = 0; kk < 12; kk++) {
            unsigned a[4];
            ldsm_x4(a, Pe + ra * 192 + ((kk * 16 + ca) ^ xa));
            #pragma unroll
            for (int np = 0; np < 4; np++) {
                unsigned b[4];
                const int vrow = kk * 16 + rv;
                ldsm_x4_trans(b, Vt + SWV(vrow, np * 16 + cv));
                mma16816(of[np * 2 + 0], a, &b[0]);
                mma16816(of[np * 2 + 1], a, &b[2]);
            }
        }
    }

    // ---- epilogue: write expanded A-pattern directly to g_atte ----
    const float inv0 = 1.0f / l0s, inv1 = 1.0f / l1s;
    const int q0 = qb * 64 + wid * 16 + g;
    #pragma unroll
    for (int n = 0; n < 8; n++) {
        const int col = h * HDIM + n * 8 + 2 * t;   // even
        {
            const float v0 = of[n][0] * inv0, v1 = of[n][1] * inv0;
            __half a0,b0,a1,b1; hsplit(v0,a0,b0); hsplit(v1,a1,b1);
            unsigned* dst = (unsigned*)(g_atte + (size_t)q0 * K3_PROJ + 3 * col);
            dst[0]=hpack(a0,a0); dst[1]=hpack(b0,a1); dst[2]=hpack(a1,b1);
        }
        {
            const float v0 = of[n][2] * inv1, v1 = of[n][3] * inv1;
            __half a0,b0,a1,b1; hsplit(v0,a0,b0); hsplit(v1,a1,b1);
            unsigned* dst = (unsigned*)(g_atte + (size_t)(q0 + 8) * K3_PROJ + 3 * col);
            dst[0]=hpack(a0,a0); dst[1]=hpack(b0,a1); dst[2]=hpack(a1,b1);
        }
    }
}

// ---------------------------------------------------------------------------
extern "C" void kernel_launch(void* const* d_in, const int* in_sizes, int n_in,
                              void* d_out, int out_size)
{
    const float* x     = (const float*)d_in[0];
    const float* W_qkv = (const float*)d_in[1];
    const float* W_out = (const float*)d_in[2];
    const float* b_out = (const float*)d_in[3];
    float* out = (float*)d_out;

    __half *xe, *wqkve, *atte, *woute;
    cudaGetSymbolAddress((void**)&xe,    g_xe);
    cudaGetSymbolAddress((void**)&wqkve, g_wqkve);
    cudaGetSymbolAddress((void**)&atte,  g_atte);
    cudaGetSymbolAddress((void**)&woute, g_woute);

    const int ATTN_SMEM = (64 * 192 + 192 * 64 + 64 * 192) * 2;   // 73728 B
    cudaFuncSetAttribute(attn_kernel, cudaFuncAttributeMaxDynamicSharedMemorySize, ATTN_SMEM);

    // 1) expand x / W_qkv for the QKV projection
    {
        int n = N_TOK * (D_MODEL / 4);
        expandA_kernel<<<(n + 255) / 256, 256>>>(x, xe, N_TOK, D_MODEL);
    }
    {
        int n = D_MODEL * QKV_N;
        expandBT_kernel<<<(n + 255) / 256, 256>>>(W_qkv, wqkve, D_MODEL, QKV_N);
    }
    // 2) QKV projection with fused Q/K/V expansion epilogue
    {
        dim3 grid(QKV_N / 128, N_TOK / 128);
        hgemm_kernel<0><<<grid, 256>>>(xe, wqkve, nullptr, nullptr, N_TOK, QKV_N, K3_PROJ);
    }
    // 3) attention (writes expanded g_atte directly)
    {
        dim3 grid(N_TOK / 64, H_HEADS);
        attn_kernel<<<grid, 128, ATTN_SMEM>>>();
    }
    // 4) expand W_out; output projection (+bias)
    {
        int n = D_MODEL * D_MODEL;
        expandBT_kernel<<<(n + 255) / 256, 256>>>(W_out, woute, D_MODEL, D_MODEL);
    }
    {
        dim3 grid(D_MODEL / 128, N_TOK / 128);
        hgemm_kernel<1><<<grid, 256>>>(atte, woute, b_out, out, N_TOK, D_MODEL, K3_PROJ);
    }
}

// round 6
// speedup vs baseline: 2.3722x; 1.5290x over previous
#include <cuda_runtime.h>
#include <cuda_fp16.h>

// Problem constants (B=1)
#define N_TOK   4096
#define D_MODEL 768
#define H_HEADS 12
#define HDIM    64
#define QKV_N   2304
#define K3_PROJ 2304
#define ATT_SCALE 0.125f

// ---------------- scratch (device globals; no runtime allocation) ----------
__device__ __align__(16) __half g_xe   [N_TOK  * K3_PROJ];
__device__ __align__(16) __half g_wqkve[QKV_N  * K3_PROJ];
__device__ __align__(16) __half g_atte [N_TOK  * K3_PROJ];
__device__ __align__(16) __half g_woute[D_MODEL* K3_PROJ];
// expanded attention operands (per head)
__device__ __align__(16) __half g_qe[H_HEADS * N_TOK * 192];   // [h][n][192] A-pattern, scaled
__device__ __align__(16) __half g_ke[H_HEADS * N_TOK * 192];   // [h][n][192] B-pattern
__device__ __align__(16) __half g_vh[H_HEADS * N_TOK * HDIM];  // [h][n][d]  plain fp16

// ---------------- helpers ---------------------------------------------------
__device__ __forceinline__ void hsplit(float x, __half& h, __half& l) {
    h = __float2half_rn(x);
    l = __float2half_rn(x - __half2float(h));
}
__device__ __forceinline__ unsigned hpack(__half a, __half b) {
    __half2 h2 = __halves2half2(a, b);
    return *reinterpret_cast<unsigned*>(&h2);
}
__device__ __forceinline__ void mma16816(float c[4], const unsigned a[4], const unsigned b[2]) {
    asm volatile(
        "mma.sync.aligned.m16n8k16.row.col.f32.f16.f16.f32 "
        "{%0,%1,%2,%3}, {%4,%5,%6,%7}, {%8,%9}, {%0,%1,%2,%3};\n"
        : "+f"(c[0]), "+f"(c[1]), "+f"(c[2]), "+f"(c[3])
        : "r"(a[0]), "r"(a[1]), "r"(a[2]), "r"(a[3]), "r"(b[0]), "r"(b[1]));
}
__device__ __forceinline__ void ldsm_x4(unsigned r[4], const __half* p) {
    unsigned addr = (unsigned)__cvta_generic_to_shared(p);
    asm volatile("ldmatrix.sync.aligned.m8n8.x4.shared.b16 {%0,%1,%2,%3}, [%4];"
                 : "=r"(r[0]), "=r"(r[1]), "=r"(r[2]), "=r"(r[3]) : "r"(addr));
}
__device__ __forceinline__ void ldsm_x4_trans(unsigned r[4], const __half* p) {
    unsigned addr = (unsigned)__cvta_generic_to_shared(p);
    asm volatile("ldmatrix.sync.aligned.m8n8.x4.trans.shared.b16 {%0,%1,%2,%3}, [%4];"
                 : "=r"(r[0]), "=r"(r[1]), "=r"(r[2]), "=r"(r[3]) : "r"(addr));
}
__device__ __forceinline__ void cp16(__half* dst, const __half* src) {
    unsigned d = (unsigned)__cvta_generic_to_shared(dst);
    asm volatile("cp.async.cg.shared.global [%0], [%1], 16;" :: "r"(d), "l"(src));
}
// swizzles: XOR at 8-half (16B) granularity
#define SW_OFF(row, col) ((row) * 192 + ((col) ^ (((row) & 7) << 3)))   // 192-half rows
#define SWV(row, col)    ((row) * 64  + ((col) ^ (((row) & 7) << 3)))   // 64-half rows
#define KV_STAGE (64 * 192 + 64 * 64)   // halfs per pipeline stage

// ---------------- input expansion kernels ------------------------------------
__global__ void expandA_kernel(const float* __restrict__ X, __half* __restrict__ Xe,
                               int M, int K)
{
    const int kq = K >> 2;
    int idx = blockIdx.x * blockDim.x + threadIdx.x;
    if (idx >= M * kq) return;
    int m = idx / kq;
    int k0 = (idx - m * kq) * 4;
    float4 v = *(const float4*)(X + (size_t)m * K + k0);
    __half h0,l0,h1,l1,h2,l2,h3,l3;
    hsplit(v.x,h0,l0); hsplit(v.y,h1,l1); hsplit(v.z,h2,l2); hsplit(v.w,h3,l3);
    unsigned* o = (unsigned*)(Xe + (size_t)m * 3 * K + 3 * k0);
    o[0]=hpack(h0,h0); o[1]=hpack(l0,h1); o[2]=hpack(h1,l1);
    o[3]=hpack(h2,h2); o[4]=hpack(l2,h3); o[5]=hpack(h3,l3);
}
__global__ void expandBT_kernel(const float* __restrict__ W, __half* __restrict__ We,
                                int K, int N)
{
    int idx = blockIdx.x * blockDim.x + threadIdx.x;
    if (idx >= K * N) return;
    int k = idx / N, n = idx - k * N;
    float x = W[(size_t)k * N + n];
    __half h, l; hsplit(x, h, l);
    __half* o = We + (size_t)n * 3 * K + 3 * k;
    o[0] = h; o[1] = l; o[2] = h;
}

// ---------------- HGEMM with fused epilogues ---------------------------------
// EPI 0: QKV — write g_qe (A-pattern, scaled) / g_ke (B-pattern) / g_vh (plain).
// EPI 1: OUT — fp32 + bias to C.
template <int EPI>
__global__ __launch_bounds__(256)
void hgemm_kernel(const __half* __restrict__ A, const __half* __restrict__ Bt,
                  const float* __restrict__ bias, float* __restrict__ C,
                  int M, int N, int K3)
{
    constexpr int LDSH = 72;
    __shared__ __align__(16) __half As[128 * LDSH];
    __shared__ __align__(16) __half Bs[128 * LDSH];

    const int tid = threadIdx.x, wid = tid >> 5, lane = tid & 31;
    const int g = lane >> 2, t = lane & 3;
    const int wm = wid & 3, wn = wid >> 2;
    const int m0 = blockIdx.y * 128, n0 = blockIdx.x * 128;
    const int NT = K3 >> 6;

    const __half* Ab = A  + (size_t)m0 * K3;
    const __half* Bb = Bt + (size_t)n0 * K3;

    const int ld_row = tid >> 3;
    const int ld_c16 = (tid & 7) * 8;

    const __half* aA = As + (wm * 32 + (lane & 15)) * LDSH + (lane >> 4) * 8;
    const __half* bB = Bs + (wn * 64 + ((lane >> 4) << 3) + (lane & 7)) * LDSH
                          + ((lane >> 3) & 1) * 8;

    uint4 ra[4], rb[4];
    #pragma unroll
    for (int i = 0; i < 4; i++) {
        int row = ld_row + i * 32;
        ra[i] = *(const uint4*)(Ab + (size_t)row * K3 + ld_c16);
        rb[i] = *(const uint4*)(Bb + (size_t)row * K3 + ld_c16);
    }
    #pragma unroll
    for (int i = 0; i < 4; i++) {
        int row = ld_row + i * 32;
        *(uint4*)(As + row * LDSH + ld_c16) = ra[i];
        *(uint4*)(Bs + row * LDSH + ld_c16) = rb[i];
    }
    __syncthreads();

    float cf[2][8][4] = {};

    for (int kt = 0; kt < NT; kt++) {
        if (kt + 1 < NT) {
            #pragma unroll
            for (int i = 0; i < 4; i++) {
                int row = ld_row + i * 32;
                ra[i] = *(const uint4*)(Ab + (size_t)row * K3 + (kt + 1) * 64 + ld_c16);
                rb[i] = *(const uint4*)(Bb + (size_t)row * K3 + (kt + 1) * 64 + ld_c16);
            }
        }
        #pragma unroll
        for (int kk = 0; kk < 4; kk++) {
            unsigned af[2][4], bf[4][4];
            #pragma unroll
            for (int mi = 0; mi < 2; mi++)
                ldsm_x4(af[mi], aA + mi * 16 * LDSH + kk * 16);
            #pragma unroll
            for (int np = 0; np < 4; np++)
                ldsm_x4(bf[np], bB + np * 16 * LDSH + kk * 16);
            #pragma unroll
            for (int mi = 0; mi < 2; mi++)
                #pragma unroll
                for (int ni = 0; ni < 8; ni++)
                    mma16816(cf[mi][ni], af[mi], &bf[ni >> 1][(ni & 1) * 2]);
        }
        __syncthreads();
        if (kt + 1 < NT) {
            #pragma unroll
            for (int i = 0; i < 4; i++) {
                int row = ld_row + i * 32;
                *(uint4*)(As + row * LDSH + ld_c16) = ra[i];
                *(uint4*)(Bs + row * LDSH + ld_c16) = rb[i];
            }
            __syncthreads();
        }
    }

    #pragma unroll
    for (int mi = 0; mi < 2; mi++) {
        const int r0 = m0 + wm * 32 + mi * 16 + g;
        #pragma unroll
        for (int ni = 0; ni < 8; ni++) {
            const int col = n0 + wn * 64 + ni * 8 + 2 * t;
            #pragma unroll
            for (int rr = 0; rr < 2; rr++) {
                const int row = r0 + rr * 8;
                const float v0 = cf[mi][ni][rr * 2 + 0];
                const float v1 = cf[mi][ni][rr * 2 + 1];
                if (EPI == 0) {
                    if (col < 768) {            // Q: A-pattern, pre-scaled
                        const int hh = col >> 6, d = col & 63;
                        __half h0,l0,h1,l1;
                        hsplit(v0 * ATT_SCALE, h0, l0);
                        hsplit(v1 * ATT_SCALE, h1, l1);
                        unsigned* dst = (unsigned*)(g_qe + ((size_t)hh * N_TOK + row) * 192 + 3 * d);
                        dst[0]=hpack(h0,h0); dst[1]=hpack(l0,h1); dst[2]=hpack(h1,l1);
                    } else if (col < 1536) {    // K: B-pattern
                        const int cc = col - 768, hh = cc >> 6, d = cc & 63;
                        __half h0,l0,h1,l1;
                        hsplit(v0, h0, l0); hsplit(v1, h1, l1);
                        unsigned* dst = (unsigned*)(g_ke + ((size_t)hh * N_TOK + row) * 192 + 3 * d);
                        dst[0]=hpack(h0,l0); dst[1]=hpack(h0,h1); dst[2]=hpack(l1,h1);
                    } else {                    // V: plain fp16
                        const int cc = col - 1536, hh = cc >> 6, d = cc & 63;
                        __half2 hv = __floats2half2_rn(v0, v1);
                        *(__half2*)(g_vh + ((size_t)hh * N_TOK + row) * HDIM + d) = hv;
                    }
                } else {
                    const float bv0 = bias[col], bv1 = bias[col + 1];
                    *(float2*)(C + (size_t)row * N + col) = make_float2(v0 + bv0, v1 + bv1);
                }
            }
        }
    }
}

// ---------------- Flash attention: reg-P, plain-fp16 PV, cp.async pipeline --
// Block = (64-query tile, head), 4 warps; warp = 16q x 64 keys, warp-local
// softmax. K (3-term) + V (plain) double-buffered via cp.async: 64 KB smem,
// 3 CTAs/SM. P fragments come straight from the S accumulators (no smem).
__global__ __launch_bounds__(128, 3)
void attn_kernel()
{
    extern __shared__ __align__(16) __half sm[];
    const int qb = blockIdx.x, h = blockIdx.y;
    const int tid = threadIdx.x, wid = tid >> 5, lane = tid & 31;
    const int g = lane >> 2, t = lane & 3;

    const __half* keg = g_ke + (size_t)h * N_TOK * 192;
    const __half* vhg = g_vh + (size_t)h * N_TOK * HDIM;

    // ---- stage Q tile in stage-0 K region; preload fragments ----
    {
        const __half* src = g_qe + ((size_t)h * N_TOK + qb * 64) * 192;
        #pragma unroll
        for (int it = 0; it < 12; it++) {
            int j = tid + it * 128;
            int r = j / 24, cj = (j % 24) * 8;
            *(uint4*)(sm + SW_OFF(r, cj)) = *(const uint4*)(src + (size_t)r * 192 + cj);
        }
    }
    __syncthreads();
    const int ra = wid * 16 + (lane & 15);
    const int xa = (ra & 7) << 3;
    const int ca = (lane >> 4) * 8;
    unsigned qf[12][4];
    #pragma unroll
    for (int kk = 0; kk < 12; kk++)
        ldsm_x4(qf[kk], sm + ra * 192 + ((kk * 16 + ca) ^ xa));
    __syncthreads();   // all Q ldsm done before cp.async overwrites stage 0

    // B-frag indices (S from K tile)
    const int rb = ((lane >> 4) << 3) + (lane & 7);
    const int xb = (rb & 7) << 3;
    const int cb = ((lane >> 3) & 1) * 8;
    // V trans-frag indices
    const int rv = lane & 15;
    const int cv = (lane >> 4) * 8;

    float of[8][4] = {};
    float m0 = -1e30f, m1 = -1e30f, l0s = 0.f, l1s = 0.f;

    // ---- prologue: async-load tile 0 into stage 0 ----
    {
        #pragma unroll
        for (int it = 0; it < 12; it++) {
            int j = tid + it * 128;
            int r = j / 24, cj = (j % 24) * 8;
            cp16(sm + SW_OFF(r, cj), keg + (size_t)r * 192 + cj);
        }
        #pragma unroll
        for (int it = 0; it < 4; it++) {
            int j = tid + it * 128;
            int r = j >> 3, cj = (j & 7) * 8;
            cp16(sm + 64 * 192 + SWV(r, cj), vhg + (size_t)r * HDIM + cj);
        }
        asm volatile("cp.async.commit_group;" ::: "memory");
    }

    for (int kb = 0; kb < N_TOK / 64; kb++) {
        const int cur = kb & 1;
        __half* KeC = sm + cur * KV_STAGE;
        __half* VhC = KeC + 64 * 192;

        if (kb + 1 < N_TOK / 64) {
            __half* KeN = sm + (cur ^ 1) * KV_STAGE;
            __half* VhN = KeN + 64 * 192;
            const __half* ks = keg + (size_t)(kb + 1) * 64 * 192;
            const __half* vs = vhg + (size_t)(kb + 1) * 64 * HDIM;
            #pragma unroll
            for (int it = 0; it < 12; it++) {
                int j = tid + it * 128;
                int r = j / 24, cj = (j % 24) * 8;
                cp16(KeN + SW_OFF(r, cj), ks + (size_t)r * 192 + cj);
            }
            #pragma unroll
            for (int it = 0; it < 4; it++) {
                int j = tid + it * 128;
                int r = j >> 3, cj = (j & 7) * 8;
                cp16(VhN + SWV(r, cj), vs + (size_t)r * HDIM + cj);
            }
            asm volatile("cp.async.commit_group;" ::: "memory");
            asm volatile("cp.async.wait_group 1;" ::: "memory");
        } else {
            asm volatile("cp.async.wait_group 0;" ::: "memory");
        }
        __syncthreads();   // current tile visible to all warps

        // ---- S = Q @ K'^T (expanded K'=192) ----
        float sf[8][4] = {};
        #pragma unroll
        for (int kk = 0; kk < 12; kk++) {
            #pragma unroll
            for (int np = 0; np < 4; np++) {
                unsigned b[4];
                ldsm_x4(b, KeC + (rb + np * 16) * 192 + ((kk * 16 + cb) ^ xb));
                mma16816(sf[np * 2 + 0], qf[kk], &b[0]);
                mma16816(sf[np * 2 + 1], qf[kk], &b[2]);
            }
        }

        // ---- warp-local online softmax -> P fragments in registers ----
        float mx0 = -1e30f, mx1 = -1e30f;
        #pragma unroll
        for (int n = 0; n < 8; n++) {
            mx0 = fmaxf(mx0, fmaxf(sf[n][0], sf[n][1]));
            mx1 = fmaxf(mx1, fmaxf(sf[n][2], sf[n][3]));
        }
        mx0 = fmaxf(mx0, __shfl_xor_sync(0xffffffffu, mx0, 1));
        mx0 = fmaxf(mx0, __shfl_xor_sync(0xffffffffu, mx0, 2));
        mx1 = fmaxf(mx1, __shfl_xor_sync(0xffffffffu, mx1, 1));
        mx1 = fmaxf(mx1, __shfl_xor_sync(0xffffffffu, mx1, 2));

        const float mn0 = fmaxf(m0, mx0), mn1 = fmaxf(m1, mx1);
        const float cr0 = __expf(m0 - mn0), cr1 = __expf(m1 - mn1);
        float rs0 = 0.f, rs1 = 0.f;

        unsigned pfA[8], pfB[8];
        #pragma unroll
        for (int n = 0; n < 8; n++) {
            float p00 = __expf(sf[n][0] - mn0);
            float p01 = __expf(sf[n][1] - mn0);
            float p10 = __expf(sf[n][2] - mn1);
            float p11 = __expf(sf[n][3] - mn1);
            rs0 += p00 + p01;
            rs1 += p10 + p11;
            __half2 ha = __floats2half2_rn(p00, p01);
            __half2 hb = __floats2half2_rn(p10, p11);
            pfA[n] = *reinterpret_cast<unsigned*>(&ha);
            pfB[n] = *reinterpret_cast<unsigned*>(&hb);
        }
        rs0 += __shfl_xor_sync(0xffffffffu, rs0, 1);
        rs0 += __shfl_xor_sync(0xffffffffu, rs0, 2);
        rs1 += __shfl_xor_sync(0xffffffffu, rs1, 1);
        rs1 += __shfl_xor_sync(0xffffffffu, rs1, 2);

        l0s = l0s * cr0 + rs0;  m0 = mn0;
        l1s = l1s * cr1 + rs1;  m1 = mn1;
        #pragma unroll
        for (int n = 0; n < 8; n++) {
            of[n][0] *= cr0; of[n][1] *= cr0;
            of[n][2] *= cr1; of[n][3] *= cr1;
        }

        // ---- O += P @ V (plain fp16, P from registers) ----
        #pragma unroll
        for (int kk = 0; kk < 4; kk++) {
            unsigned a[4] = {pfA[2 * kk], pfB[2 * kk], pfA[2 * kk + 1], pfB[2 * kk + 1]};
            #pragma unroll
            for (int np = 0; np < 4; np++) {
                unsigned b[4];
                ldsm_x4_trans(b, VhC + SWV(kk * 16 + rv, np * 16 + cv));
                mma16816(of[np * 2 + 0], a, &b[0]);
                mma16816(of[np * 2 + 1], a, &b[2]);
            }
        }
        __syncthreads();   // all reads of current stage done before it is refilled
    }

    // ---- epilogue: write expanded A-pattern directly to g_atte ----
    const float inv0 = 1.0f / l0s, inv1 = 1.0f / l1s;
    const int q0 = qb * 64 + wid * 16 + g;
    #pragma unroll
    for (int n = 0; n < 8; n++) {
        const int col = h * HDIM + n * 8 + 2 * t;   // even
        {
            const float v0 = of[n][0] * inv0, v1 = of[n][1] * inv0;
            __half a0,b0,a1,b1; hsplit(v0,a0,b0); hsplit(v1,a1,b1);
            unsigned* dst = (unsigned*)(g_atte + (size_t)q0 * K3_PROJ + 3 * col);
            dst[0]=hpack(a0,a0); dst[1]=hpack(b0,a1); dst[2]=hpack(a1,b1);
        }
        {
            const float v0 = of[n][2] * inv1, v1 = of[n][3] * inv1;
            __half a0,b0,a1,b1; hsplit(v0,a0,b0); hsplit(v1,a1,b1);
            unsigned* dst = (unsigned*)(g_atte + (size_t)(q0 + 8) * K3_PROJ + 3 * col);
            dst[0]=hpack(a0,a0); dst[1]=hpack(b0,a1); dst[2]=hpack(a1,b1);
        }
    }
}

// ---------------------------------------------------------------------------
extern "C" void kernel_launch(void* const* d_in, const int* in_sizes, int n_in,
                              void* d_out, int out_size)
{
    const float* x     = (const float*)d_in[0];
    const float* W_qkv = (const float*)d_in[1];
    const float* W_out = (const float*)d_in[2];
    const float* b_out = (const float*)d_in[3];
    float* out = (float*)d_out;

    __half *xe, *wqkve, *atte, *woute;
    cudaGetSymbolAddress((void**)&xe,    g_xe);
    cudaGetSymbolAddress((void**)&wqkve, g_wqkve);
    cudaGetSymbolAddress((void**)&atte,  g_atte);
    cudaGetSymbolAddress((void**)&woute, g_woute);

    const int ATTN_SMEM = 2 * KV_STAGE * 2;   // 65536 B
    cudaFuncSetAttribute(attn_kernel, cudaFuncAttributeMaxDynamicSharedMemorySize, ATTN_SMEM);

    // 1) expand x / W_qkv for the QKV projection
    {
        int n = N_TOK * (D_MODEL / 4);
        expandA_kernel<<<(n + 255) / 256, 256>>>(x, xe, N_TOK, D_MODEL);
    }
    {
        int n = D_MODEL * QKV_N;
        expandBT_kernel<<<(n + 255) / 256, 256>>>(W_qkv, wqkve, D_MODEL, QKV_N);
    }
    // 2) QKV projection with fused Q/K/V expansion epilogue
    {
        dim3 grid(QKV_N / 128, N_TOK / 128);
        hgemm_kernel<0><<<grid, 256>>>(xe, wqkve, nullptr, nullptr, N_TOK, QKV_N, K3_PROJ);
    }
    // 3) attention (writes expanded g_atte directly)
    {
        dim3 grid(N_TOK / 64, H_HEADS);
        attn_kernel<<<grid, 128, ATTN_SMEM>>>();
    }
    // 4) expand W_out; output projection (+bias)
    {
        int n = D_MODEL * D_MODEL;
        expandBT_kernel<<<(n + 255) / 256, 256>>>(W_out, woute, D_MODEL, D_MODEL);
    }
    {
        dim3 grid(D_MODEL / 128, N_TOK / 128);
        hgemm_kernel<1><<<grid, 256>>>(atte, woute, b_out, out, N_TOK, D_MODEL, K3_PROJ);
    }
}

// round 7
// speedup vs baseline: 2.4977x; 1.0529x over previous
#include <cuda_runtime.h>
#include <cuda_fp16.h>

// Problem constants (B=1)
#define N_TOK   4096
#define D_MODEL 768
#define H_HEADS 12
#define HDIM    64
#define QKV_N   2304
#define K3_PROJ 2304
#define ATT_SCALE 0.125f
#define LOG2E 1.4426950408889634f

// ---------------- scratch (device globals; no runtime allocation) ----------
__device__ __align__(16) __half g_xe   [N_TOK  * K3_PROJ];
__device__ __align__(16) __half g_wqkve[QKV_N  * K3_PROJ];
__device__ __align__(16) __half g_atte [N_TOK  * K3_PROJ];
__device__ __align__(16) __half g_woute[D_MODEL* K3_PROJ];
// expanded attention operands (per head)
__device__ __align__(16) __half g_qe[H_HEADS * N_TOK * 192];   // [h][n][192] A-pattern, scale*log2e
__device__ __align__(16) __half g_ke[H_HEADS * N_TOK * 192];   // [h][n][192] B-pattern
__device__ __align__(16) __half g_vh[H_HEADS * N_TOK * HDIM];  // [h][n][d]  plain fp16

// ---------------- helpers ---------------------------------------------------
__device__ __forceinline__ void hsplit(float x, __half& h, __half& l) {
    h = __float2half_rn(x);
    l = __float2half_rn(x - __half2float(h));
}
__device__ __forceinline__ unsigned hpack(__half a, __half b) {
    __half2 h2 = __halves2half2(a, b);
    return *reinterpret_cast<unsigned*>(&h2);
}
__device__ __forceinline__ float ex2f(float x) {
    float r;
    asm("ex2.approx.f32 %0, %1;" : "=f"(r) : "f"(x));
    return r;
}
__device__ __forceinline__ void mma16816(float c[4], const unsigned a[4], const unsigned b[2]) {
    asm volatile(
        "mma.sync.aligned.m16n8k16.row.col.f32.f16.f16.f32 "
        "{%0,%1,%2,%3}, {%4,%5,%6,%7}, {%8,%9}, {%0,%1,%2,%3};\n"
        : "+f"(c[0]), "+f"(c[1]), "+f"(c[2]), "+f"(c[3])
        : "r"(a[0]), "r"(a[1]), "r"(a[2]), "r"(a[3]), "r"(b[0]), "r"(b[1]));
}
__device__ __forceinline__ void ldsm_x4(unsigned r[4], const __half* p) {
    unsigned addr = (unsigned)__cvta_generic_to_shared(p);
    asm volatile("ldmatrix.sync.aligned.m8n8.x4.shared.b16 {%0,%1,%2,%3}, [%4];"
                 : "=r"(r[0]), "=r"(r[1]), "=r"(r[2]), "=r"(r[3]) : "r"(addr));
}
__device__ __forceinline__ void ldsm_x4_trans(unsigned r[4], const __half* p) {
    unsigned addr = (unsigned)__cvta_generic_to_shared(p);
    asm volatile("ldmatrix.sync.aligned.m8n8.x4.trans.shared.b16 {%0,%1,%2,%3}, [%4];"
                 : "=r"(r[0]), "=r"(r[1]), "=r"(r[2]), "=r"(r[3]) : "r"(addr));
}
__device__ __forceinline__ void cp16(__half* dst, const __half* src) {
    unsigned d = (unsigned)__cvta_generic_to_shared(dst);
    asm volatile("cp.async.cg.shared.global [%0], [%1], 16;" :: "r"(d), "l"(src));
}
// swizzles: XOR at 8-half (16B) granularity
#define SW_OFF(row, col) ((row) * 192 + ((col) ^ (((row) & 7) << 3)))   // 192-half rows
#define SWV(row, col)    ((row) * 64  + ((col) ^ (((row) & 7) << 3)))   // 64-half rows
#define KV_STAGE (64 * 192 + 64 * 64)   // halfs per K/V pipeline stage
#define QS_HALFS (128 * 192)            // persistent Q region (halfs)

// ---------------- input expansion kernels ------------------------------------
__global__ void expandA_kernel(const float* __restrict__ X, __half* __restrict__ Xe,
                               int M, int K)
{
    const int kq = K >> 2;
    int idx = blockIdx.x * blockDim.x + threadIdx.x;
    if (idx >= M * kq) return;
    int m = idx / kq;
    int k0 = (idx - m * kq) * 4;
    float4 v = *(const float4*)(X + (size_t)m * K + k0);
    __half h0,l0,h1,l1,h2,l2,h3,l3;
    hsplit(v.x,h0,l0); hsplit(v.y,h1,l1); hsplit(v.z,h2,l2); hsplit(v.w,h3,l3);
    unsigned* o = (unsigned*)(Xe + (size_t)m * 3 * K + 3 * k0);
    o[0]=hpack(h0,h0); o[1]=hpack(l0,h1); o[2]=hpack(h1,l1);
    o[3]=hpack(h2,h2); o[4]=hpack(l2,h3); o[5]=hpack(h3,l3);
}
__global__ void expandBT_kernel(const float* __restrict__ W, __half* __restrict__ We,
                                int K, int N)
{
    int idx = blockIdx.x * blockDim.x + threadIdx.x;
    if (idx >= K * N) return;
    int k = idx / N, n = idx - k * N;
    float x = W[(size_t)k * N + n];
    __half h, l; hsplit(x, h, l);
    __half* o = We + (size_t)n * 3 * K + 3 * k;
    o[0] = h; o[1] = l; o[2] = h;
}

// ---------------- HGEMM, cp.async double-buffered ----------------------------
// EPI 0: QKV — write g_qe (A-pattern, scale*log2e) / g_ke (B-pattern) / g_vh.
// EPI 1: OUT — fp32 + bias to C.
#define LDSH 72
#define GSTG (2 * 128 * LDSH)   // halfs per stage (A tile + B tile)

template <int EPI>
__global__ __launch_bounds__(256)
void hgemm_kernel(const __half* __restrict__ A, const __half* __restrict__ Bt,
                  const float* __restrict__ bias, float* __restrict__ C,
                  int M, int N, int K3)
{
    extern __shared__ __align__(16) __half gsm[];

    const int tid = threadIdx.x, wid = tid >> 5, lane = tid & 31;
    const int g = lane >> 2, t = lane & 3;
    const int wm = wid & 3, wn = wid >> 2;
    const int m0 = blockIdx.y * 128, n0 = blockIdx.x * 128;
    const int NT = K3 >> 6;

    const __half* Ab = A  + (size_t)m0 * K3;
    const __half* Bb = Bt + (size_t)n0 * K3;

    const int ld_row = tid >> 3;        // 0..31 (+32 per i)
    const int ld_c16 = (tid & 7) * 8;

    const int aoff = (wm * 32 + (lane & 15)) * LDSH + (lane >> 4) * 8;
    const int boff = (wn * 64 + ((lane >> 4) << 3) + (lane & 7)) * LDSH
                     + ((lane >> 3) & 1) * 8;

    // prologue: prefetch tile 0 into stage 0
    {
        __half* As0 = gsm;
        __half* Bs0 = gsm + 128 * LDSH;
        #pragma unroll
        for (int i = 0; i < 4; i++) {
            int row = ld_row + i * 32;
            cp16(As0 + row * LDSH + ld_c16, Ab + (size_t)row * K3 + ld_c16);
            cp16(Bs0 + row * LDSH + ld_c16, Bb + (size_t)row * K3 + ld_c16);
        }
        asm volatile("cp.async.commit_group;" ::: "memory");
    }

    float cf[2][8][4] = {};

    for (int kt = 0; kt < NT; kt++) {
        const int cur = kt & 1;
        if (kt + 1 < NT) {
            __half* AsN = gsm + (cur ^ 1) * GSTG;
            __half* BsN = AsN + 128 * LDSH;
            const int ko = (kt + 1) * 64;
            #pragma unroll
            for (int i = 0; i < 4; i++) {
                int row = ld_row + i * 32;
                cp16(AsN + row * LDSH + ld_c16, Ab + (size_t)row * K3 + ko + ld_c16);
                cp16(BsN + row * LDSH + ld_c16, Bb + (size_t)row * K3 + ko + ld_c16);
            }
            asm volatile("cp.async.commit_group;" ::: "memory");
            asm volatile("cp.async.wait_group 1;" ::: "memory");
        } else {
            asm volatile("cp.async.wait_group 0;" ::: "memory");
        }
        __syncthreads();

        const __half* aA = gsm + cur * GSTG + aoff;
        const __half* bB = gsm + cur * GSTG + 128 * LDSH + boff;

        #pragma unroll
        for (int kk = 0; kk < 4; kk++) {
            unsigned af[2][4], bf[4][4];
            #pragma unroll
            for (int mi = 0; mi < 2; mi++)
                ldsm_x4(af[mi], aA + mi * 16 * LDSH + kk * 16);
            #pragma unroll
            for (int np = 0; np < 4; np++)
                ldsm_x4(bf[np], bB + np * 16 * LDSH + kk * 16);
            #pragma unroll
            for (int mi = 0; mi < 2; mi++)
                #pragma unroll
                for (int ni = 0; ni < 8; ni++)
                    mma16816(cf[mi][ni], af[mi], &bf[ni >> 1][(ni & 1) * 2]);
        }
        __syncthreads();   // all reads of stage `cur` done before it is refilled
    }

    #pragma unroll
    for (int mi = 0; mi < 2; mi++) {
        const int r0 = m0 + wm * 32 + mi * 16 + g;
        #pragma unroll
        for (int ni = 0; ni < 8; ni++) {
            const int col = n0 + wn * 64 + ni * 8 + 2 * t;
            #pragma unroll
            for (int rr = 0; rr < 2; rr++) {
                const int row = r0 + rr * 8;
                const float v0 = cf[mi][ni][rr * 2 + 0];
                const float v1 = cf[mi][ni][rr * 2 + 1];
                if (EPI == 0) {
                    if (col < 768) {            // Q: A-pattern, scale*log2e
                        const int hh = col >> 6, d = col & 63;
                        __half h0,l0,h1,l1;
                        hsplit(v0 * (ATT_SCALE * LOG2E), h0, l0);
                        hsplit(v1 * (ATT_SCALE * LOG2E), h1, l1);
                        unsigned* dst = (unsigned*)(g_qe + ((size_t)hh * N_TOK + row) * 192 + 3 * d);
                        dst[0]=hpack(h0,h0); dst[1]=hpack(l0,h1); dst[2]=hpack(h1,l1);
                    } else if (col < 1536) {    // K: B-pattern
                        const int cc = col - 768, hh = cc >> 6, d = cc & 63;
                        __half h0,l0,h1,l1;
                        hsplit(v0, h0, l0); hsplit(v1, h1, l1);
                        unsigned* dst = (unsigned*)(g_ke + ((size_t)hh * N_TOK + row) * 192 + 3 * d);
                        dst[0]=hpack(h0,l0); dst[1]=hpack(h0,h1); dst[2]=hpack(l1,h1);
                    } else {                    // V: plain fp16
                        const int cc = col - 1536, hh = cc >> 6, d = cc & 63;
                        __half2 hv = __floats2half2_rn(v0, v1);
                        *(__half2*)(g_vh + ((size_t)hh * N_TOK + row) * HDIM + d) = hv;
                    }
                } else {
                    const float bv0 = bias[col], bv1 = bias[col + 1];
                    *(float2*)(C + (size_t)row * N + col) = make_float2(v0 + bv0, v1 + bv1);
                }
            }
        }
    }
}

// ---------------- Flash attention: Br=128, 8 warps, Q in persistent smem ----
// warp = 16q x 64 keys, warp-local softmax, P fragments from registers.
// smem = Q[128][192] + 2 stages of (K[64][192] + V[64][64]) = 112 KB
// -> 2 CTAs/SM (16 warps). exp in base-2 (Q pre-scaled by log2e).
__global__ __launch_bounds__(256, 2)
void attn_kernel()
{
    extern __shared__ __align__(16) __half sm[];
    __half* Qs = sm;                     // [128][192] swizzled, persistent
    __half* ST = sm + QS_HALFS;          // 2 x KV_STAGE

    const int qb = blockIdx.x, h = blockIdx.y;
    const int tid = threadIdx.x, wid = tid >> 5, lane = tid & 31;
    const int g = lane >> 2, t = lane & 3;

    const __half* keg = g_ke + (size_t)h * N_TOK * 192;
    const __half* vhg = g_vh + (size_t)h * N_TOK * HDIM;

    // ---- stage Q tile (persistent) ----
    {
        const __half* src = g_qe + ((size_t)h * N_TOK + qb * 128) * 192;
        #pragma unroll
        for (int it = 0; it < 12; it++) {
            int j = tid + it * 256;
            int r = j / 24, cj = (j % 24) * 8;
            *(uint4*)(Qs + SW_OFF(r, cj)) = *(const uint4*)(src + (size_t)r * 192 + cj);
        }
    }

    // frag indices
    const int ra = wid * 16 + (lane & 15);       // Q row
    const int xa = (ra & 7) << 3;
    const int ca = (lane >> 4) * 8;
    const int rb = ((lane >> 4) << 3) + (lane & 7);   // K row
    const int xb = (rb & 7) << 3;
    const int cb = ((lane >> 3) & 1) * 8;
    const int rv = lane & 15;                    // V row-within-chunk
    const int cv = (lane >> 4) * 8;

    float of[8][4] = {};
    float m0 = -1e30f, m1 = -1e30f, l0s = 0.f, l1s = 0.f;

    // ---- prologue: async-load K/V tile 0 into stage 0 ----
    {
        #pragma unroll
        for (int it = 0; it < 6; it++) {
            int j = tid + it * 256;
            int r = j / 24, cj = (j % 24) * 8;
            cp16(ST + SW_OFF(r, cj), keg + (size_t)r * 192 + cj);
        }
        #pragma unroll
        for (int it = 0; it < 2; it++) {
            int j = tid + it * 256;
            int r = j >> 3, cj = (j & 7) * 8;
            cp16(ST + 64 * 192 + SWV(r, cj), vhg + (size_t)r * HDIM + cj);
        }
        asm volatile("cp.async.commit_group;" ::: "memory");
    }
    __syncthreads();   // Q stores visible to all warps (overlapped with cp.async)

    for (int kb = 0; kb < N_TOK / 64; kb++) {
        const int cur = kb & 1;
        __half* KeC = ST + cur * KV_STAGE;
        __half* VhC = KeC + 64 * 192;

        if (kb + 1 < N_TOK / 64) {
            __half* KeN = ST + (cur ^ 1) * KV_STAGE;
            __half* VhN = KeN + 64 * 192;
            const __half* ks = keg + (size_t)(kb + 1) * 64 * 192;
            const __half* vs = vhg + (size_t)(kb + 1) * 64 * HDIM;
            #pragma unroll
            for (int it = 0; it < 6; it++) {
                int j = tid + it * 256;
                int r = j / 24, cj = (j % 24) * 8;
                cp16(KeN + SW_OFF(r, cj), ks + (size_t)r * 192 + cj);
            }
            #pragma unroll
            for (int it = 0; it < 2; it++) {
                int j = tid + it * 256;
                int r = j >> 3, cj = (j & 7) * 8;
                cp16(VhN + SWV(r, cj), vs + (size_t)r * HDIM + cj);
            }
            asm volatile("cp.async.commit_group;" ::: "memory");
            asm volatile("cp.async.wait_group 1;" ::: "memory");
        } else {
            asm volatile("cp.async.wait_group 0;" ::: "memory");
        }
        __syncthreads();

        // ---- S = Q @ K'^T (expanded K'=192), base-2 scores ----
        float sf[8][4] = {};
        #pragma unroll
        for (int kk = 0; kk < 12; kk++) {
            unsigned a[4];
            ldsm_x4(a, Qs + ra * 192 + ((kk * 16 + ca) ^ xa));
            #pragma unroll
            for (int np = 0; np < 4; np++) {
                unsigned b[4];
                ldsm_x4(b, KeC + (rb + np * 16) * 192 + ((kk * 16 + cb) ^ xb));
                mma16816(sf[np * 2 + 0], a, &b[0]);
                mma16816(sf[np * 2 + 1], a, &b[2]);
            }
        }

        // ---- warp-local online softmax (base 2) ----
        float mx0 = -1e30f, mx1 = -1e30f;
        #pragma unroll
        for (int n = 0; n < 8; n++) {
            mx0 = fmaxf(mx0, fmaxf(sf[n][0], sf[n][1]));
            mx1 = fmaxf(mx1, fmaxf(sf[n][2], sf[n][3]));
        }
        mx0 = fmaxf(mx0, __shfl_xor_sync(0xffffffffu, mx0, 1));
        mx0 = fmaxf(mx0, __shfl_xor_sync(0xffffffffu, mx0, 2));
        mx1 = fmaxf(mx1, __shfl_xor_sync(0xffffffffu, mx1, 1));
        mx1 = fmaxf(mx1, __shfl_xor_sync(0xffffffffu, mx1, 2));

        const float mn0 = fmaxf(m0, mx0), mn1 = fmaxf(m1, mx1);
        const float cr0 = ex2f(m0 - mn0), cr1 = ex2f(m1 - mn1);
        float rs0 = 0.f, rs1 = 0.f;

        unsigned pfA[8], pfB[8];
        #pragma unroll
        for (int n = 0; n < 8; n++) {
            float p00 = ex2f(sf[n][0] - mn0);
            float p01 = ex2f(sf[n][1] - mn0);
            float p10 = ex2f(sf[n][2] - mn1);
            float p11 = ex2f(sf[n][3] - mn1);
            rs0 += p00 + p01;
            rs1 += p10 + p11;
            __half2 ha = __floats2half2_rn(p00, p01);
            __half2 hb = __floats2half2_rn(p10, p11);
            pfA[n] = *reinterpret_cast<unsigned*>(&ha);
            pfB[n] = *reinterpret_cast<unsigned*>(&hb);
        }
        rs0 += __shfl_xor_sync(0xffffffffu, rs0, 1);
        rs0 += __shfl_xor_sync(0xffffffffu, rs0, 2);
        rs1 += __shfl_xor_sync(0xffffffffu, rs1, 1);
        rs1 += __shfl_xor_sync(0xffffffffu, rs1, 2);

        l0s = l0s * cr0 + rs0;  m0 = mn0;
        l1s = l1s * cr1 + rs1;  m1 = mn1;
        #pragma unroll
        for (int n = 0; n < 8; n++) {
            of[n][0] *= cr0; of[n][1] *= cr0;
            of[n][2] *= cr1; of[n][3] *= cr1;
        }

        // ---- O += P @ V (plain fp16, P from registers) ----
        #pragma unroll
        for (int kk = 0; kk < 4; kk++) {
            unsigned a[4] = {pfA[2 * kk], pfB[2 * kk], pfA[2 * kk + 1], pfB[2 * kk + 1]};
            #pragma unroll
            for (int np = 0; np < 4; np++) {
                unsigned b[4];
                ldsm_x4_trans(b, VhC + SWV(kk * 16 + rv, np * 16 + cv));
                mma16816(of[np * 2 + 0], a, &b[0]);
                mma16816(of[np * 2 + 1], a, &b[2]);
            }
        }
        __syncthreads();   // all reads of current stage done before refill
    }

    // ---- epilogue: write expanded A-pattern directly to g_atte ----
    const float inv0 = 1.0f / l0s, inv1 = 1.0f / l1s;
    const int q0 = qb * 128 + wid * 16 + g;
    #pragma unroll
    for (int n = 0; n < 8; n++) {
        const int col = h * HDIM + n * 8 + 2 * t;   // even
        {
            const float v0 = of[n][0] * inv0, v1 = of[n][1] * inv0;
            __half a0,b0,a1,b1; hsplit(v0,a0,b0); hsplit(v1,a1,b1);
            unsigned* dst = (unsigned*)(g_atte + (size_t)q0 * K3_PROJ + 3 * col);
            dst[0]=hpack(a0,a0); dst[1]=hpack(b0,a1); dst[2]=hpack(a1,b1);
        }
        {
            const float v0 = of[n][2] * inv1, v1 = of[n][3] * inv1;
            __half a0,b0,a1,b1; hsplit(v0,a0,b0); hsplit(v1,a1,b1);
            unsigned* dst = (unsigned*)(g_atte + (size_t)(q0 + 8) * K3_PROJ + 3 * col);
            dst[0]=hpack(a0,a0); dst[1]=hpack(b0,a1); dst[2]=hpack(a1,b1);
        }
    }
}

// ---------------------------------------------------------------------------
extern "C" void kernel_launch(void* const* d_in, const int* in_sizes, int n_in,
                              void* d_out, int out_size)
{
    const float* x     = (const float*)d_in[0];
    const float* W_qkv = (const float*)d_in[1];
    const float* W_out = (const float*)d_in[2];
    const float* b_out = (const float*)d_in[3];
    float* out = (float*)d_out;

    __half *xe, *wqkve, *atte, *woute;
    cudaGetSymbolAddress((void**)&xe,    g_xe);
    cudaGetSymbolAddress((void**)&wqkve, g_wqkve);
    cudaGetSymbolAddress((void**)&atte,  g_atte);
    cudaGetSymbolAddress((void**)&woute, g_woute);

    const int GEMM_SMEM = 2 * GSTG * 2;                       // 73728 B
    const int ATTN_SMEM = (QS_HALFS + 2 * KV_STAGE) * 2;      // 114688 B
    cudaFuncSetAttribute(hgemm_kernel<0>, cudaFuncAttributeMaxDynamicSharedMemorySize, GEMM_SMEM);
    cudaFuncSetAttribute(hgemm_kernel<1>, cudaFuncAttributeMaxDynamicSharedMemorySize, GEMM_SMEM);
    cudaFuncSetAttribute(attn_kernel, cudaFuncAttributeMaxDynamicSharedMemorySize, ATTN_SMEM);

    // 1) expand x / W_qkv for the QKV projection
    {
        int n = N_TOK * (D_MODEL / 4);
        expandA_kernel<<<(n + 255) / 256, 256>>>(x, xe, N_TOK, D_MODEL);
    }
    {
        int n = D_MODEL * QKV_N;
        expandBT_kernel<<<(n + 255) / 256, 256>>>(W_qkv, wqkve, D_MODEL, QKV_N);
    }
    // 2) QKV projection with fused Q/K/V expansion epilogue
    {
        dim3 grid(QKV_N / 128, N_TOK / 128);
        hgemm_kernel<0><<<grid, 256, GEMM_SMEM>>>(xe, wqkve, nullptr, nullptr,
                                                  N_TOK, QKV_N, K3_PROJ);
    }
    // 3) attention (writes expanded g_atte directly)
    {
        dim3 grid(N_TOK / 128, H_HEADS);
        attn_kernel<<<grid, 256, ATTN_SMEM>>>();
    }
    // 4) expand W_out; output projection (+bias)
    {
        int n = D_MODEL * D_MODEL;
        expandBT_kernel<<<(n + 255) / 256, 256>>>(W_out, woute, D_MODEL, D_MODEL);
    }
    {
        dim3 grid(D_MODEL / 128, N_TOK / 128);
        hgemm_kernel<1><<<grid, 256, GEMM_SMEM>>>(atte, woute, b_out, out,
                                                  N_TOK, D_MODEL, K3_PROJ);
    }
}